// round 11
// baseline (speedup 1.0000x reference)
#include <cuda_runtime.h>
#include <cuda_fp16.h>
#include <cstdint>

#define NB   64
#define NC   256
#define NL   4096
#define NOUT 256
#define NTOK (NB * NL)   // 262144 tokens

// ================= helpers =================
__device__ __forceinline__ uint32_t smem_to_u32(const void* p) {
    uint32_t a;
    asm("{ .reg .u64 t; cvta.to.shared.u64 t, %1; cvt.u32.u64 %0, t; }" : "=r"(a) : "l"(p));
    return a;
}
__device__ __forceinline__ void cpa16(uint32_t s, const void* g) {
    asm volatile("cp.async.cg.shared.global [%0], [%1], 16;" :: "r"(s), "l"(g) : "memory");
}
__device__ __forceinline__ uint32_t lds32v(uint32_t a) {
    uint32_t v;
    asm volatile("ld.shared.b32 %0, [%1];" : "=r"(v) : "r"(a) : "memory");
    return v;
}
__device__ __forceinline__ uint32_t lds_u16pair(uint32_t a0, uint32_t a1) {
    uint32_t lo, hi;
    asm volatile("ld.shared.u16 %0, [%1];" : "=r"(lo) : "r"(a0) : "memory");
    asm volatile("ld.shared.u16 %0, [%1];" : "=r"(hi) : "r"(a1) : "memory");
    return lo | (hi << 16);
}
#define MMAF16(d, a, b) \
    asm volatile("mma.sync.aligned.m16n8k16.row.col.f32.f16.f16.f32 " \
        "{%0,%1,%2,%3},{%4,%5,%6,%7},{%8,%9},{%0,%1,%2,%3};" \
        : "+f"((d)[0]), "+f"((d)[1]), "+f"((d)[2]), "+f"((d)[3]) \
        : "r"((a)[0]), "r"((a)[1]), "r"((a)[2]), "r"((a)[3]), "r"((b)[0]), "r"((b)[1]))

// ================= scratch (device globals; referenced ONLY in device code) =================
__device__ __align__(256) __half g_xh  [(long long)NTOK * NC];
__device__ __align__(256) __half g_xl  [(long long)NTOK * NC];
__device__ __align__(256) __half g_zf  [(long long)NTOK * NC];
__device__ __align__(256) __half g_vf  [(long long)NTOK * NC];
__device__ __align__(256) float  g_virt[(long long)NTOK * NC];
__device__ __align__(256) __half g_nh  [(long long)NTOK * NC];
__device__ __align__(256) __half g_nl  [(long long)NTOK * NC];
__device__ __align__(256) __half g_Gf [NC * NC];
__device__ __align__(256) __half g_wvf[NC * NC];
__device__ __align__(256) __half g_wof[NC * NC];
__device__ __align__(256) __half g_wzf[NC * NC];
__device__ float g_psum[NB], g_psumsq[NB], g_mean[NB], g_rstd[NB];

// ================= K: zero GN accumulators =================
__global__ void k_zero()
{
    int t = threadIdx.x;
    if (t < NB) { g_psum[t] = 0.f; g_psumsq[t] = 0.f; }
}

// ================= K: transpose x -> fp16 hi/lo split (token-major) =================
__global__ __launch_bounds__(256) void k_prep0(const float* __restrict__ x)
{
    __shared__ float tile[64][65];
    const int b  = blockIdx.z;
    const int l0 = blockIdx.x << 6;
    const int c0 = blockIdx.y << 6;
    const int tid = threadIdx.x;
    const int tx = tid & 63, ty = tid >> 6;

    const float* xp = x + (size_t)b * NC * NL + (size_t)c0 * NL + l0;
#pragma unroll
    for (int i = 0; i < 16; i++) {
        int r = i * 4 + ty;
        tile[r][tx] = xp[(size_t)r * NL + tx];
    }
    __syncthreads();
#pragma unroll
    for (int i = 0; i < 16; i++) {
        int lr = i * 4 + ty;
        float v = tile[tx][lr];
        size_t idx = ((size_t)(b * NL + l0 + lr)) * NC + c0 + tx;
        __half h = __float2half(v);
        g_xh[idx] = h;
        g_xl[idx] = __float2half(v - __half2float(h));
    }
}

// ================= K: G[e][f] = sum_o Wq[o][e] Wk[o][f] -> fp16 =================
__global__ __launch_bounds__(256) void k_gmatA(const float* __restrict__ Wq, const float* __restrict__ Wk)
{
    __shared__ float sA[16][68], sB[16][68];
    const int e0 = (blockIdx.x & 3) << 6;
    const int f0 = (blockIdx.x >> 2) << 6;
    const int tid = threadIdx.x;
    const int tx = tid & 15, ty = tid >> 4;

    float acc[4][4];
#pragma unroll
    for (int i = 0; i < 4; i++)
#pragma unroll
        for (int j = 0; j < 4; j++) acc[i][j] = 0.f;

    for (int k0 = 0; k0 < NC; k0 += 16) {
#pragma unroll
        for (int i = 0; i < 4; i++) {
            int r = (tid >> 6) + i * 4, col = tid & 63;
            sA[r][col] = Wq[(size_t)(k0 + r) * NC + e0 + col];
            sB[r][col] = Wk[(size_t)(k0 + r) * NC + f0 + col];
        }
        __syncthreads();
#pragma unroll
        for (int kk = 0; kk < 16; kk++) {
            float a[4], bb[4];
#pragma unroll
            for (int i = 0; i < 4; i++) { a[i] = sA[kk][ty * 4 + i]; bb[i] = sB[kk][tx * 4 + i]; }
#pragma unroll
            for (int i = 0; i < 4; i++)
#pragma unroll
                for (int j = 0; j < 4; j++) acc[i][j] = fmaf(a[i], bb[j], acc[i][j]);
        }
        __syncthreads();
    }
#pragma unroll
    for (int i = 0; i < 4; i++)
#pragma unroll
        for (int j = 0; j < 4; j++)
            g_Gf[(e0 + ty * 4 + i) * NC + f0 + tx * 4 + j] = __float2half(acc[i][j]);
}

// ================= K: Wz[o][c] = sum_m Wout[o][m] Wc[m][c] -> fp16 =================
__global__ __launch_bounds__(256) void k_gmatB(const float* __restrict__ Wo, const float* __restrict__ Wc)
{
    __shared__ float sA[16][68], sB[16][68];
    const int e0 = (blockIdx.x & 3) << 6;      // o tile
    const int f0 = (blockIdx.x >> 2) << 6;     // c tile
    const int tid = threadIdx.x;
    const int tx = tid & 15, ty = tid >> 4;

    float acc[4][4];
#pragma unroll
    for (int i = 0; i < 4; i++)
#pragma unroll
        for (int j = 0; j < 4; j++) acc[i][j] = 0.f;

    for (int k0 = 0; k0 < NC; k0 += 16) {
#pragma unroll
        for (int i = 0; i < 4; i++) {
            int r = (tid >> 6) + i * 4, col = tid & 63;
            sA[r][col] = Wo[(size_t)(e0 + col) * NC + k0 + r];   // transposed gather
            sB[r][col] = Wc[(size_t)(k0 + r) * NC + f0 + col];
        }
        __syncthreads();
#pragma unroll
        for (int kk = 0; kk < 16; kk++) {
            float a[4], bb[4];
#pragma unroll
            for (int i = 0; i < 4; i++) { a[i] = sA[kk][ty * 4 + i]; bb[i] = sB[kk][tx * 4 + i]; }
#pragma unroll
            for (int i = 0; i < 4; i++)
#pragma unroll
                for (int j = 0; j < 4; j++) acc[i][j] = fmaf(a[i], bb[j], acc[i][j]);
        }
        __syncthreads();
    }
#pragma unroll
    for (int i = 0; i < 4; i++)
#pragma unroll
        for (int j = 0; j < 4; j++)
            g_wzf[(e0 + ty * 4 + i) * NC + f0 + tx * 4 + j] = __float2half(acc[i][j]);
}

// ================= K: round Wv, Wout to fp16 =================
__global__ __launch_bounds__(256) void k_prepw(
    const float* __restrict__ Wv, const float* __restrict__ Wo)
{
    int gid = blockIdx.x * 256 + threadIdx.x;
    int arr = gid >> 14;
    int off = (gid & 16383) * 4;
    const float* src = (arr == 0) ? Wv : Wo;
    __half* dst = (arr == 0) ? g_wvf : g_wof;
    float4 v = *(const float4*)(src + off);
    __half2 h0; h0.x = __float2half(v.x); h0.y = __float2half(v.y);
    __half2 h1; h1.x = __float2half(v.z); h1.y = __float2half(v.w);
    *(__half2*)(dst + off)     = h0;
    *(__half2*)(dst + off + 2) = h1;
}

// ================= K: fp16 one-sided-split GEMM, 4-stage pipeline =================
// A split (hi/lo), W single fp16.  C = Ah*W + Al*W.
// A smem row 80B: [hi k0-7|hi k8-15|lo k0-7|lo k8-15|pad]; W row 48B: [k0-7|k8-15|pad].
// KIND 0: grid (2048, 4): y<2 -> z = G x (fp16 out) ; y>=2 -> v = Wv x (fp16 out)
// KIND 1: grid (2048, 2): out = Wout x + Wz gn (K=512, transposed fp32 store)
#define AROWB   80
#define WROWB   48
#define HALF_A  (128 * AROWB)                 // 10240
#define STAGE_B (HALF_A + 128 * WROWB)        // 16384
#define NPIPE   4
#define SMEM_GEMM (NPIPE * STAGE_B)           // 65536

template<int KIND>
__global__ __launch_bounds__(256) void k_gemm(float* __restrict__ outf)
{
    extern __shared__ __align__(128) char smem[];
    const uint32_t sbase = smem_to_u32(smem);
    const int tid  = threadIdx.x;
    const int wid  = tid >> 5;
    const int lane = tid & 31;
    const int t0   = blockIdx.x << 7;
    const int NS   = (KIND == 0) ? 16 : 32;

    int o0, wsel = 0;
    if (KIND == 0) { wsel = blockIdx.y >> 1; o0 = (blockIdx.y & 1) << 7; }
    else           { o0 = blockIdx.y << 7; }

    const int wm = wid & 1;
    const int wn = wid >> 1;

    auto load_stage = [&](int s) {
        const __half *Ah, *Al, *Wf;
        int k0;
        if (KIND == 0) {
            Ah = g_xh; Al = g_xl;
            Wf = wsel ? g_wvf : g_Gf;
            k0 = s << 4;
        } else {
            if (s < 16) { Ah = g_xh; Al = g_xl; Wf = g_wof; k0 = s << 4; }
            else        { Ah = g_nh; Al = g_nl; Wf = g_wzf; k0 = (s - 16) << 4; }
        }
        const uint32_t buf = sbase + (uint32_t)(s & (NPIPE - 1)) * STAGE_B;
#pragma unroll
        for (int i = 0; i < 3; i++) {
            int idx = tid + (i << 8);          // [0,768)
            if (idx < 512) {
                int r = idx >> 2, ch = idx & 3;
                const __half* src = ((ch < 2) ? Ah : Al) + (size_t)(t0 + r) * NC + k0 + ((ch & 1) << 3);
                cpa16(buf + (uint32_t)(r * AROWB + (ch << 4)), src);
            } else {
                int j = idx - 512;
                int r = j >> 1, ch = j & 1;
                const __half* src = Wf + (size_t)(o0 + r) * NC + k0 + (ch << 3);
                cpa16(buf + (uint32_t)HALF_A + (uint32_t)(r * WROWB + (ch << 4)), src);
            }
        }
        asm volatile("cp.async.commit_group;" ::: "memory");
    };

    float acc[4][4][4];
#pragma unroll
    for (int a = 0; a < 4; a++)
#pragma unroll
        for (int b = 0; b < 4; b++)
#pragma unroll
            for (int c = 0; c < 4; c++) acc[a][b][c] = 0.f;

    const int rq = lane >> 2;
    const int p4 = (lane & 3) << 2;

    load_stage(0);
    load_stage(1);
    load_stage(2);

    for (int s = 0; s < NS; s++) {
        int rem = NS - 1 - s;
        if (rem >= 2)      asm volatile("cp.async.wait_group 2;" ::: "memory");
        else if (rem == 1) asm volatile("cp.async.wait_group 1;" ::: "memory");
        else               asm volatile("cp.async.wait_group 0;" ::: "memory");
        __syncthreads();
        if (s + 3 < NS) load_stage(s + 3);

        const uint32_t bufA = sbase + (uint32_t)(s & (NPIPE - 1)) * STAGE_B;
        const uint32_t bufW = bufA + (uint32_t)HALF_A;

        uint32_t ah[4][4], al[4][4], bf[4][2];
#pragma unroll
        for (int mt = 0; mt < 4; mt++) {
            uint32_t base = bufA + (uint32_t)((wm * 64 + mt * 16 + rq) * AROWB + p4);
            ah[mt][0] = lds32v(base);
            ah[mt][1] = lds32v(base + 8 * AROWB);
            ah[mt][2] = lds32v(base + 16);
            ah[mt][3] = lds32v(base + 8 * AROWB + 16);
            al[mt][0] = lds32v(base + 32);
            al[mt][1] = lds32v(base + 8 * AROWB + 32);
            al[mt][2] = lds32v(base + 48);
            al[mt][3] = lds32v(base + 8 * AROWB + 48);
        }
#pragma unroll
        for (int nt = 0; nt < 4; nt++) {
            uint32_t base = bufW + (uint32_t)((wn * 32 + nt * 8 + rq) * WROWB + p4);
            bf[nt][0] = lds32v(base);
            bf[nt][1] = lds32v(base + 16);
        }
#pragma unroll
        for (int mt = 0; mt < 4; mt++)
#pragma unroll
            for (int nt = 0; nt < 4; nt++) {
                MMAF16(acc[mt][nt], ah[mt], bf[nt]);
                MMAF16(acc[mt][nt], al[mt], bf[nt]);
            }
    }

    // epilogue
    const int fr = lane >> 2;
    const int fc = (lane & 3) * 2;
#pragma unroll
    for (int mt = 0; mt < 4; mt++) {
#pragma unroll
        for (int nt = 0; nt < 4; nt++) {
            int r = wm * 64 + mt * 16 + fr;
            int c = wn * 32 + nt * 8 + fc;
            float d0 = acc[mt][nt][0], d1 = acc[mt][nt][1];
            float d2 = acc[mt][nt][2], d3 = acc[mt][nt][3];
            if (KIND == 0) {
                __half* dst = wsel ? g_vf : g_zf;
                __half2 h01; h01.x = __float2half(d0); h01.y = __float2half(d1);
                __half2 h23; h23.x = __float2half(d2); h23.y = __float2half(d3);
                *(__half2*)(dst + (size_t)(t0 + r) * NC + o0 + c)     = h01;
                *(__half2*)(dst + (size_t)(t0 + r + 8) * NC + o0 + c) = h23;
            } else {
                const int b = t0 >> 12;
                int l = (t0 & 4095) + r;
                outf[((size_t)(b * NOUT + o0 + c))     * NL + l] = d0;
                outf[((size_t)(b * NOUT + o0 + c + 1)) * NL + l] = d1;
                outf[((size_t)(b * NOUT + o0 + c))     * NL + l + 8] = d2;
                outf[((size_t)(b * NOUT + o0 + c + 1)) * NL + l + 8] = d3;
            }
        }
    }
}

// ================= K: tensorized per-l batch attention + GN partials =================
// smem bytes: QH 0 (64x528), QL 33792, K 67584 (64x528, single fp16),
//   S 101376 (fp32 [64][68], reused as GN accum), AH 118784 (64x144),
//   AL 128000, V 137216 (2 x 64x144 single fp16)
#define OF_QH 0
#define OF_QL 33792
#define OF_K  67584
#define OF_S  101376
#define OF_AH 118784
#define OF_AL 128000
#define OF_V  137216
#define SM_ATTN_BYTES (OF_V + 2 * 9216)   // 155648

__global__ __launch_bounds__(256) void k_attn()
{
    extern __shared__ __align__(128) char smc[];
    const uint32_t S0 = smem_to_u32(smc);
    float* smf = (float*)smc;
    const int l = blockIdx.x;
    const int tid = threadIdx.x;
    const int wid = tid >> 5, lane = tid & 31;
    const int rq = lane >> 2, p4 = (lane & 3) << 2;
    const int m0 = (wid & 3) * 16;
    const int n0 = (wid >> 2) * 32;

    // ---- load Q(x hi/lo) and K(z single) ----
    for (int idx = tid; idx < 2048; idx += 256) {
        int row = idx >> 5, ch = idx & 31;
        size_t g = ((size_t)row * NL + l) * NC + ch * 8;
        uint32_t so = (uint32_t)(row * 528 + ch * 16);
        cpa16(S0 + OF_QH + so, g_xh + g);
        cpa16(S0 + OF_QL + so, g_xl + g);
        cpa16(S0 + OF_K  + so, g_zf + g);
    }
    // V chunk 0 into buffer 0
    for (int idx = tid; idx < 512; idx += 256) {
        int d = idx >> 3, ch = idx & 7;
        size_t g = ((size_t)d * NL + l) * NC + ch * 8;
        cpa16(S0 + OF_V + (uint32_t)(d * 144 + ch * 16), g_vf + g);
    }
    asm volatile("cp.async.commit_group;" ::: "memory");
    asm volatile("cp.async.wait_group 0;" ::: "memory");
    __syncthreads();

    // ---- scores S[b][d] = (x_b . z_d)/16 ; 2-term one-sided split ----
    float acc[4][4];
#pragma unroll
    for (int i = 0; i < 4; i++)
#pragma unroll
        for (int j = 0; j < 4; j++) acc[i][j] = 0.f;

#pragma unroll
    for (int kk = 0; kk < 16; kk++) {
        uint32_t abase = S0 + (uint32_t)((m0 + rq) * 528 + kk * 32 + p4);
        uint32_t ah[4], al[4];
        ah[0] = lds32v(abase + OF_QH);
        ah[1] = lds32v(abase + OF_QH + 8 * 528);
        ah[2] = lds32v(abase + OF_QH + 16);
        ah[3] = lds32v(abase + OF_QH + 8 * 528 + 16);
        al[0] = lds32v(abase + OF_QL);
        al[1] = lds32v(abase + OF_QL + 8 * 528);
        al[2] = lds32v(abase + OF_QL + 16);
        al[3] = lds32v(abase + OF_QL + 8 * 528 + 16);
#pragma unroll
        for (int nt = 0; nt < 4; nt++) {
            uint32_t bbase = S0 + OF_K + (uint32_t)((n0 + nt * 8 + rq) * 528 + kk * 32 + p4);
            uint32_t bf[2];
            bf[0] = lds32v(bbase);
            bf[1] = lds32v(bbase + 16);
            MMAF16(acc[nt], ah, bf);
            MMAF16(acc[nt], al, bf);
        }
    }
#pragma unroll
    for (int nt = 0; nt < 4; nt++) {
        int r = m0 + rq;
        int c = n0 + nt * 8 + (lane & 3) * 2;
        *(float2*)&smf[(OF_S >> 2) + r * 68 + c]       = make_float2(acc[nt][0] * 0.0625f, acc[nt][1] * 0.0625f);
        *(float2*)&smf[(OF_S >> 2) + (r + 8) * 68 + c] = make_float2(acc[nt][2] * 0.0625f, acc[nt][3] * 0.0625f);
    }
    __syncthreads();

    // ---- softmax over d, write att as fp16 hi/lo ----
    if (tid < 64) {
        float* row = &smf[(OF_S >> 2) + tid * 68];
        float m = row[0];
        for (int d = 1; d < 64; d++) m = fmaxf(m, row[d]);
        float s = 0.f;
        float e[64];
        for (int d = 0; d < 64; d++) { e[d] = __expf(row[d] - m); s += e[d]; }
        float inv = 1.f / s;
        for (int d = 0; d < 64; d += 2) {
            float w0 = e[d] * inv, w1 = e[d + 1] * inv;
            __half h0 = __float2half(w0);
            __half h1 = __float2half(w1);
            __half2 hh; hh.x = h0; hh.y = h1;
            *(__half2*)(smc + OF_AH + tid * 144 + d * 2) = hh;
            __half2 ll;
            ll.x = __float2half(w0 - __half2float(h0));
            ll.y = __float2half(w1 - __half2float(h1));
            *(__half2*)(smc + OF_AL + tid * 144 + d * 2) = ll;
        }
        smf[(OF_S >> 2) + tid] = 0.f;        // GN sum
        smf[(OF_S >> 2) + 64 + tid] = 0.f;   // GN sumsq
    }

    // ---- AV: virt[b][c] = sum_d att[b][d] v[d][c], chunked over c ----
    float gs0 = 0.f, gss0 = 0.f, gs1 = 0.f, gss1 = 0.f;

    for (int cc = 0; cc < 4; cc++) {
        __syncthreads();
        if (cc < 3) {
            int nb = (cc + 1) & 1;
            for (int idx = tid; idx < 512; idx += 256) {
                int d = idx >> 3, ch = idx & 7;
                size_t g = ((size_t)d * NL + l) * NC + (cc + 1) * 64 + ch * 8;
                cpa16(S0 + OF_V + (uint32_t)(nb * 9216 + d * 144 + ch * 16), g_vf + g);
            }
            asm volatile("cp.async.commit_group;" ::: "memory");
            asm volatile("cp.async.wait_group 1;" ::: "memory");
        } else {
            asm volatile("cp.async.wait_group 0;" ::: "memory");
        }
        __syncthreads();

        const uint32_t VB = S0 + OF_V + (uint32_t)((cc & 1) * 9216);

        float av[4][4];
#pragma unroll
        for (int i = 0; i < 4; i++)
#pragma unroll
            for (int j = 0; j < 4; j++) av[i][j] = 0.f;

#pragma unroll
        for (int k = 0; k < 4; k++) {
            uint32_t abase = S0 + (uint32_t)((m0 + rq) * 144 + k * 32 + p4);
            uint32_t ah[4], al[4];
            ah[0] = lds32v(abase + OF_AH);
            ah[1] = lds32v(abase + OF_AH + 8 * 144);
            ah[2] = lds32v(abase + OF_AH + 16);
            ah[3] = lds32v(abase + OF_AH + 8 * 144 + 16);
            al[0] = lds32v(abase + OF_AL);
            al[1] = lds32v(abase + OF_AL + 8 * 144);
            al[2] = lds32v(abase + OF_AL + 16);
            al[3] = lds32v(abase + OF_AL + 8 * 144 + 16);
            int d0 = k * 16 + (lane & 3) * 2;
#pragma unroll
            for (int nt = 0; nt < 4; nt++) {
                int c = n0 + nt * 8 + rq;
                uint32_t a0 = VB + (uint32_t)(d0 * 144 + c * 2);
                uint32_t bf[2];
                bf[0] = lds_u16pair(a0, a0 + 144);
                bf[1] = lds_u16pair(a0 + 8 * 144, a0 + 9 * 144);
                MMAF16(av[nt], ah, bf);
                MMAF16(av[nt], al, bf);
            }
        }
#pragma unroll
        for (int nt = 0; nt < 4; nt++) {
            int b0r = m0 + rq;
            int c = cc * 64 + n0 + nt * 8 + (lane & 3) * 2;
            float2 v01 = make_float2(av[nt][0], av[nt][1]);
            float2 v23 = make_float2(av[nt][2], av[nt][3]);
            *(float2*)(g_virt + ((size_t)b0r * NL + l) * NC + c)       = v01;
            *(float2*)(g_virt + ((size_t)(b0r + 8) * NL + l) * NC + c) = v23;
            gs0  += v01.x + v01.y;
            gss0 += v01.x * v01.x + v01.y * v01.y;
            gs1  += v23.x + v23.y;
            gss1 += v23.x * v23.x + v23.y * v23.y;
        }
    }

    gs0  += __shfl_xor_sync(0xffffffffu, gs0, 1);  gs0  += __shfl_xor_sync(0xffffffffu, gs0, 2);
    gss0 += __shfl_xor_sync(0xffffffffu, gss0, 1); gss0 += __shfl_xor_sync(0xffffffffu, gss0, 2);
    gs1  += __shfl_xor_sync(0xffffffffu, gs1, 1);  gs1  += __shfl_xor_sync(0xffffffffu, gs1, 2);
    gss1 += __shfl_xor_sync(0xffffffffu, gss1, 1); gss1 += __shfl_xor_sync(0xffffffffu, gss1, 2);
    if ((lane & 3) == 0) {
        atomicAdd(&smf[(OF_S >> 2) + m0 + rq], gs0);
        atomicAdd(&smf[(OF_S >> 2) + 64 + m0 + rq], gss0);
        atomicAdd(&smf[(OF_S >> 2) + m0 + rq + 8], gs1);
        atomicAdd(&smf[(OF_S >> 2) + 64 + m0 + rq + 8], gss1);
    }
    __syncthreads();
    if (tid < 64) {
        atomicAdd(&g_psum[tid],   smf[(OF_S >> 2) + tid]);
        atomicAdd(&g_psumsq[tid], smf[(OF_S >> 2) + 64 + tid]);
    }
}

// ================= K: stats =================
__global__ void k_stats()
{
    int b = threadIdx.x;
    if (b < NB) {
        const float n = (float)NC * (float)NL;
        float mean = g_psum[b] / n;
        float var  = g_psumsq[b] / n - mean * mean;
        if (var < 0.f) var = 0.f;
        g_mean[b] = mean;
        g_rstd[b] = rsqrtf(var + 1e-5f);
    }
}

// ================= K: GN+ReLU on virt -> fp16 hi/lo =================
__global__ __launch_bounds__(256) void k_prep2(const float* __restrict__ gamma, const float* __restrict__ beta)
{
    size_t i4 = ((size_t)blockIdx.x * 256 + threadIdx.x) * 4;
    int c = (int)(i4 & 255);
    int b = (int)(i4 >> 20);
    float mean = g_mean[b], rstd = g_rstd[b];
    float4 v = *(const float4*)(g_virt + i4);
    float vv[4] = { v.x, v.y, v.z, v.w };
#pragma unroll
    for (int i = 0; i < 4; i++) {
        float y = fmaxf(fmaf((vv[i] - mean) * rstd, gamma[c + i], beta[c + i]), 0.f);
        __half h = __float2half(y);
        g_nh[i4 + i] = h;
        g_nl[i4 + i] = __float2half(y - __half2float(h));
    }
}

// ================= launch =================
extern "C" void kernel_launch(void* const* d_in, const int* in_sizes, int n_in,
                              void* d_out, int out_size)
{
    const float* x     = (const float*)d_in[0];
    const float* Wq    = (const float*)d_in[1];
    const float* Wk    = (const float*)d_in[2];
    const float* Wv    = (const float*)d_in[3];
    const float* Wc    = (const float*)d_in[4];
    const float* Wout  = (const float*)d_in[5];
    const float* gamma = (const float*)d_in[6];
    const float* beta  = (const float*)d_in[7];
    float* out = (float*)d_out;

    cudaFuncSetAttribute(k_attn,    cudaFuncAttributeMaxDynamicSharedMemorySize, SM_ATTN_BYTES);
    cudaFuncSetAttribute(k_gemm<0>, cudaFuncAttributeMaxDynamicSharedMemorySize, SMEM_GEMM);
    cudaFuncSetAttribute(k_gemm<1>, cudaFuncAttributeMaxDynamicSharedMemorySize, SMEM_GEMM);

    k_zero<<<1, 128>>>();
    k_prep0<<<dim3(64, 4, 64), 256>>>(x);
    k_gmatA<<<16, 256>>>(Wq, Wk);
    k_gmatB<<<16, 256>>>(Wout, Wc);
    k_prepw<<<128, 256>>>(Wv, Wout);
    k_gemm<0><<<dim3(2048, 4), 256, SMEM_GEMM>>>(nullptr);   // z,v (fp16)
    k_attn<<<NL, 256, SM_ATTN_BYTES>>>();
    k_stats<<<1, 64>>>();
    k_prep2<<<65536, 256>>>(gamma, beta);
    k_gemm<1><<<dim3(2048, 2), 256, SMEM_GEMM>>>(out);       // out = Wout x + Wz gn
}

// round 12
// speedup vs baseline: 1.5259x; 1.5259x over previous
#include <cuda_runtime.h>
#include <cuda_fp16.h>
#include <cstdint>

#define NB   64
#define NC   256
#define NL   4096
#define NOUT 256
#define NTOK (NB * NL)   // 262144 tokens

// ================= helpers =================
__device__ __forceinline__ uint32_t smem_to_u32(const void* p) {
    uint32_t a;
    asm("{ .reg .u64 t; cvta.to.shared.u64 t, %1; cvt.u32.u64 %0, t; }" : "=r"(a) : "l"(p));
    return a;
}
__device__ __forceinline__ void cpa16(uint32_t s, const void* g) {
    asm volatile("cp.async.cg.shared.global [%0], [%1], 16;" :: "r"(s), "l"(g) : "memory");
}
__device__ __forceinline__ uint32_t lds32v(uint32_t a) {
    uint32_t v;
    asm volatile("ld.shared.b32 %0, [%1];" : "=r"(v) : "r"(a) : "memory");
    return v;
}
__device__ __forceinline__ uint32_t lds_u16pair(uint32_t a0, uint32_t a1) {
    uint32_t lo, hi;
    asm volatile("ld.shared.u16 %0, [%1];" : "=r"(lo) : "r"(a0) : "memory");
    asm volatile("ld.shared.u16 %0, [%1];" : "=r"(hi) : "r"(a1) : "memory");
    return lo | (hi << 16);
}
#define MMAF16(d, a, b) \
    asm volatile("mma.sync.aligned.m16n8k16.row.col.f32.f16.f16.f32 " \
        "{%0,%1,%2,%3},{%4,%5,%6,%7},{%8,%9},{%0,%1,%2,%3};" \
        : "+f"((d)[0]), "+f"((d)[1]), "+f"((d)[2]), "+f"((d)[3]) \
        : "r"((a)[0]), "r"((a)[1]), "r"((a)[2]), "r"((a)[3]), "r"((b)[0]), "r"((b)[1]))

// ================= scratch (device globals; referenced ONLY in device code) =================
__device__ __align__(256) __half g_xh  [(long long)NTOK * NC];
__device__ __align__(256) __half g_xl  [(long long)NTOK * NC];
__device__ __align__(256) __half g_zf  [(long long)NTOK * NC];
__device__ __align__(256) __half g_vf  [(long long)NTOK * NC];
__device__ __align__(256) float  g_virt[(long long)NTOK * NC];
__device__ __align__(256) __half g_nh  [(long long)NTOK * NC];
__device__ __align__(256) __half g_nl  [(long long)NTOK * NC];
__device__ __align__(256) __half g_Gf [NC * NC];
__device__ __align__(256) __half g_wvf[NC * NC];
__device__ __align__(256) __half g_wof[NC * NC];
__device__ __align__(256) __half g_wzf[NC * NC];
__device__ float g_psum[NB], g_psumsq[NB], g_mean[NB], g_rstd[NB];

// ================= K: zero GN accumulators =================
__global__ void k_zero()
{
    int t = threadIdx.x;
    if (t < NB) { g_psum[t] = 0.f; g_psumsq[t] = 0.f; }
}

// ================= K: transpose x -> fp16 hi/lo split (token-major) =================
__global__ __launch_bounds__(256) void k_prep0(const float* __restrict__ x)
{
    __shared__ float tile[64][65];
    const int b  = blockIdx.z;
    const int l0 = blockIdx.x << 6;
    const int c0 = blockIdx.y << 6;
    const int tid = threadIdx.x;
    const int tx = tid & 63, ty = tid >> 6;

    const float* xp = x + (size_t)b * NC * NL + (size_t)c0 * NL + l0;
#pragma unroll
    for (int i = 0; i < 16; i++) {
        int r = i * 4 + ty;
        tile[r][tx] = xp[(size_t)r * NL + tx];
    }
    __syncthreads();
#pragma unroll
    for (int i = 0; i < 16; i++) {
        int lr = i * 4 + ty;
        float v = tile[tx][lr];
        size_t idx = ((size_t)(b * NL + l0 + lr)) * NC + c0 + tx;
        __half h = __float2half(v);
        g_xh[idx] = h;
        g_xl[idx] = __float2half(v - __half2float(h));
    }
}

// ================= K: G[e][f] = sum_o Wq[o][e] Wk[o][f] -> fp16 =================
__global__ __launch_bounds__(256) void k_gmatA(const float* __restrict__ Wq, const float* __restrict__ Wk)
{
    __shared__ float sA[16][68], sB[16][68];
    const int e0 = (blockIdx.x & 3) << 6;
    const int f0 = (blockIdx.x >> 2) << 6;
    const int tid = threadIdx.x;
    const int tx = tid & 15, ty = tid >> 4;

    float acc[4][4];
#pragma unroll
    for (int i = 0; i < 4; i++)
#pragma unroll
        for (int j = 0; j < 4; j++) acc[i][j] = 0.f;

    for (int k0 = 0; k0 < NC; k0 += 16) {
#pragma unroll
        for (int i = 0; i < 4; i++) {
            int r = (tid >> 6) + i * 4, col = tid & 63;
            sA[r][col] = Wq[(size_t)(k0 + r) * NC + e0 + col];
            sB[r][col] = Wk[(size_t)(k0 + r) * NC + f0 + col];
        }
        __syncthreads();
#pragma unroll
        for (int kk = 0; kk < 16; kk++) {
            float a[4], bb[4];
#pragma unroll
            for (int i = 0; i < 4; i++) { a[i] = sA[kk][ty * 4 + i]; bb[i] = sB[kk][tx * 4 + i]; }
#pragma unroll
            for (int i = 0; i < 4; i++)
#pragma unroll
                for (int j = 0; j < 4; j++) acc[i][j] = fmaf(a[i], bb[j], acc[i][j]);
        }
        __syncthreads();
    }
#pragma unroll
    for (int i = 0; i < 4; i++)
#pragma unroll
        for (int j = 0; j < 4; j++)
            g_Gf[(e0 + ty * 4 + i) * NC + f0 + tx * 4 + j] = __float2half(acc[i][j]);
}

// ================= K: Wz[o][c] = sum_m Wout[o][m] Wc[m][c] -> fp16 =================
__global__ __launch_bounds__(256) void k_gmatB(const float* __restrict__ Wo, const float* __restrict__ Wc)
{
    __shared__ float sA[16][68], sB[16][68];
    const int e0 = (blockIdx.x & 3) << 6;      // o tile
    const int f0 = (blockIdx.x >> 2) << 6;     // c tile
    const int tid = threadIdx.x;
    const int tx = tid & 15, ty = tid >> 4;

    float acc[4][4];
#pragma unroll
    for (int i = 0; i < 4; i++)
#pragma unroll
        for (int j = 0; j < 4; j++) acc[i][j] = 0.f;

    for (int k0 = 0; k0 < NC; k0 += 16) {
#pragma unroll
        for (int i = 0; i < 4; i++) {
            int r = (tid >> 6) + i * 4, col = tid & 63;
            sA[r][col] = Wo[(size_t)(e0 + col) * NC + k0 + r];   // transposed gather
            sB[r][col] = Wc[(size_t)(k0 + r) * NC + f0 + col];
        }
        __syncthreads();
#pragma unroll
        for (int kk = 0; kk < 16; kk++) {
            float a[4], bb[4];
#pragma unroll
            for (int i = 0; i < 4; i++) { a[i] = sA[kk][ty * 4 + i]; bb[i] = sB[kk][tx * 4 + i]; }
#pragma unroll
            for (int i = 0; i < 4; i++)
#pragma unroll
                for (int j = 0; j < 4; j++) acc[i][j] = fmaf(a[i], bb[j], acc[i][j]);
        }
        __syncthreads();
    }
#pragma unroll
    for (int i = 0; i < 4; i++)
#pragma unroll
        for (int j = 0; j < 4; j++)
            g_wzf[(e0 + ty * 4 + i) * NC + f0 + tx * 4 + j] = __float2half(acc[i][j]);
}

// ================= K: round Wv, Wout to fp16 =================
__global__ __launch_bounds__(256) void k_prepw(
    const float* __restrict__ Wv, const float* __restrict__ Wo)
{
    int gid = blockIdx.x * 256 + threadIdx.x;
    int arr = gid >> 14;
    int off = (gid & 16383) * 4;
    const float* src = (arr == 0) ? Wv : Wo;
    __half* dst = (arr == 0) ? g_wvf : g_wof;
    float4 v = *(const float4*)(src + off);
    __half2 h0; h0.x = __float2half(v.x); h0.y = __float2half(v.y);
    __half2 h1; h1.x = __float2half(v.z); h1.y = __float2half(v.w);
    *(__half2*)(dst + off)     = h0;
    *(__half2*)(dst + off + 2) = h1;
}

// ================= K: fp16 one-sided-split GEMM, 4-stage pipeline =================
// A split (hi/lo), W single fp16.  C = Ah*W + Al*W.
// A smem row 80B: [hi k0-7|hi k8-15|lo k0-7|lo k8-15|pad]; W row 48B.
// KIND 0: grid (2048, 4): y<2 -> z = G x (fp16 out) ; y>=2 -> v = Wv x (fp16 out)
// KIND 1: grid (2048, 2): out = Wout x + Wz gn (K=512, transposed fp32 store)
#define AROWB   80
#define WROWB   48
#define HALF_A  (128 * AROWB)                 // 10240
#define STAGE_B (HALF_A + 128 * WROWB)        // 16384
#define NPIPE   4
#define SMEM_GEMM (NPIPE * STAGE_B)           // 65536

template<int KIND>
__global__ __launch_bounds__(256) void k_gemm(float* __restrict__ outf)
{
    extern __shared__ __align__(128) char smem[];
    const uint32_t sbase = smem_to_u32(smem);
    const int tid  = threadIdx.x;
    const int wid  = tid >> 5;
    const int lane = tid & 31;
    const int t0   = blockIdx.x << 7;
    const int NS   = (KIND == 0) ? 16 : 32;

    int o0, wsel = 0;
    if (KIND == 0) { wsel = blockIdx.y >> 1; o0 = (blockIdx.y & 1) << 7; }
    else           { o0 = blockIdx.y << 7; }

    const int wm = wid & 1;
    const int wn = wid >> 1;

    auto load_stage = [&](int s) {
        const __half *Ah, *Al, *Wf;
        int k0;
        if (KIND == 0) {
            Ah = g_xh; Al = g_xl;
            Wf = wsel ? g_wvf : g_Gf;
            k0 = s << 4;
        } else {
            if (s < 16) { Ah = g_xh; Al = g_xl; Wf = g_wof; k0 = s << 4; }
            else        { Ah = g_nh; Al = g_nl; Wf = g_wzf; k0 = (s - 16) << 4; }
        }
        const uint32_t buf = sbase + (uint32_t)(s & (NPIPE - 1)) * STAGE_B;
#pragma unroll
        for (int i = 0; i < 3; i++) {
            int idx = tid + (i << 8);          // [0,768)
            if (idx < 512) {
                int r = idx >> 2, ch = idx & 3;
                const __half* src = ((ch < 2) ? Ah : Al) + (size_t)(t0 + r) * NC + k0 + ((ch & 1) << 3);
                cpa16(buf + (uint32_t)(r * AROWB + (ch << 4)), src);
            } else {
                int j = idx - 512;
                int r = j >> 1, ch = j & 1;
                const __half* src = Wf + (size_t)(o0 + r) * NC + k0 + (ch << 3);
                cpa16(buf + (uint32_t)HALF_A + (uint32_t)(r * WROWB + (ch << 4)), src);
            }
        }
        asm volatile("cp.async.commit_group;" ::: "memory");
    };

    float acc[4][4][4];
#pragma unroll
    for (int a = 0; a < 4; a++)
#pragma unroll
        for (int b = 0; b < 4; b++)
#pragma unroll
            for (int c = 0; c < 4; c++) acc[a][b][c] = 0.f;

    const int rq = lane >> 2;
    const int p4 = (lane & 3) << 2;

    load_stage(0);
    load_stage(1);
    load_stage(2);

    for (int s = 0; s < NS; s++) {
        int rem = NS - 1 - s;
        if (rem >= 2)      asm volatile("cp.async.wait_group 2;" ::: "memory");
        else if (rem == 1) asm volatile("cp.async.wait_group 1;" ::: "memory");
        else               asm volatile("cp.async.wait_group 0;" ::: "memory");
        __syncthreads();
        if (s + 3 < NS) load_stage(s + 3);

        const uint32_t bufA = sbase + (uint32_t)(s & (NPIPE - 1)) * STAGE_B;
        const uint32_t bufW = bufA + (uint32_t)HALF_A;

        uint32_t ah[4][4], al[4][4], bf[4][2];
#pragma unroll
        for (int mt = 0; mt < 4; mt++) {
            uint32_t base = bufA + (uint32_t)((wm * 64 + mt * 16 + rq) * AROWB + p4);
            ah[mt][0] = lds32v(base);
            ah[mt][1] = lds32v(base + 8 * AROWB);
            ah[mt][2] = lds32v(base + 16);
            ah[mt][3] = lds32v(base + 8 * AROWB + 16);
            al[mt][0] = lds32v(base + 32);
            al[mt][1] = lds32v(base + 8 * AROWB + 32);
            al[mt][2] = lds32v(base + 48);
            al[mt][3] = lds32v(base + 8 * AROWB + 48);
        }
#pragma unroll
        for (int nt = 0; nt < 4; nt++) {
            uint32_t base = bufW + (uint32_t)((wn * 32 + nt * 8 + rq) * WROWB + p4);
            bf[nt][0] = lds32v(base);
            bf[nt][1] = lds32v(base + 16);
        }
#pragma unroll
        for (int mt = 0; mt < 4; mt++)
#pragma unroll
            for (int nt = 0; nt < 4; nt++) {
                MMAF16(acc[mt][nt], ah[mt], bf[nt]);
                MMAF16(acc[mt][nt], al[mt], bf[nt]);
            }
    }

    // epilogue
    const int fr = lane >> 2;
    const int fc = (lane & 3) * 2;
#pragma unroll
    for (int mt = 0; mt < 4; mt++) {
#pragma unroll
        for (int nt = 0; nt < 4; nt++) {
            int r = wm * 64 + mt * 16 + fr;
            int c = wn * 32 + nt * 8 + fc;
            float d0 = acc[mt][nt][0], d1 = acc[mt][nt][1];
            float d2 = acc[mt][nt][2], d3 = acc[mt][nt][3];
            if (KIND == 0) {
                __half* dst = wsel ? g_vf : g_zf;
                __half2 h01; h01.x = __float2half(d0); h01.y = __float2half(d1);
                __half2 h23; h23.x = __float2half(d2); h23.y = __float2half(d3);
                *(__half2*)(dst + (size_t)(t0 + r) * NC + o0 + c)     = h01;
                *(__half2*)(dst + (size_t)(t0 + r + 8) * NC + o0 + c) = h23;
            } else {
                const int b = t0 >> 12;
                int l = (t0 & 4095) + r;
                outf[((size_t)(b * NOUT + o0 + c))     * NL + l] = d0;
                outf[((size_t)(b * NOUT + o0 + c + 1)) * NL + l] = d1;
                outf[((size_t)(b * NOUT + o0 + c))     * NL + l + 8] = d2;
                outf[((size_t)(b * NOUT + o0 + c + 1)) * NL + l + 8] = d3;
            }
        }
    }
}

// ================= K: tensorized per-l batch attention + GN partials =================
// smem bytes: QH 0 (64x528), QL 33792, K 67584 (64x528, single fp16),
//   S 101376 (fp32 [64][68], reused as GN accum), AH 118784 (64x144),
//   AL 128000, V 137216 (2 x 64x144 single fp16)
#define OF_QH 0
#define OF_QL 33792
#define OF_K  67584
#define OF_S  101376
#define OF_AH 118784
#define OF_AL 128000
#define OF_V  137216
#define SM_ATTN_BYTES (OF_V + 2 * 9216)   // 155648

__global__ __launch_bounds__(256) void k_attn()
{
    extern __shared__ __align__(128) char smc[];
    const uint32_t S0 = smem_to_u32(smc);
    float* smf = (float*)smc;
    const int l = blockIdx.x;
    const int tid = threadIdx.x;
    const int wid = tid >> 5, lane = tid & 31;
    const int rq = lane >> 2, p4 = (lane & 3) << 2;
    const int m0 = (wid & 3) * 16;
    const int n0 = (wid >> 2) * 32;

    // ---- load Q(x hi/lo) and K(z single) ----
    for (int idx = tid; idx < 2048; idx += 256) {
        int row = idx >> 5, ch = idx & 31;
        size_t g = ((size_t)row * NL + l) * NC + ch * 8;
        uint32_t so = (uint32_t)(row * 528 + ch * 16);
        cpa16(S0 + OF_QH + so, g_xh + g);
        cpa16(S0 + OF_QL + so, g_xl + g);
        cpa16(S0 + OF_K  + so, g_zf + g);
    }
    // V chunk 0 into buffer 0
    for (int idx = tid; idx < 512; idx += 256) {
        int d = idx >> 3, ch = idx & 7;
        size_t g = ((size_t)d * NL + l) * NC + ch * 8;
        cpa16(S0 + OF_V + (uint32_t)(d * 144 + ch * 16), g_vf + g);
    }
    asm volatile("cp.async.commit_group;" ::: "memory");
    asm volatile("cp.async.wait_group 0;" ::: "memory");
    __syncthreads();

    // ---- scores S[b][d] = (x_b . z_d)/16 ; 2-term one-sided split ----
    float acc[4][4];
#pragma unroll
    for (int i = 0; i < 4; i++)
#pragma unroll
        for (int j = 0; j < 4; j++) acc[i][j] = 0.f;

#pragma unroll
    for (int kk = 0; kk < 16; kk++) {
        uint32_t abase = S0 + (uint32_t)((m0 + rq) * 528 + kk * 32 + p4);
        uint32_t ah[4], al[4];
        ah[0] = lds32v(abase + OF_QH);
        ah[1] = lds32v(abase + OF_QH + 8 * 528);
        ah[2] = lds32v(abase + OF_QH + 16);
        ah[3] = lds32v(abase + OF_QH + 8 * 528 + 16);
        al[0] = lds32v(abase + OF_QL);
        al[1] = lds32v(abase + OF_QL + 8 * 528);
        al[2] = lds32v(abase + OF_QL + 16);
        al[3] = lds32v(abase + OF_QL + 8 * 528 + 16);
#pragma unroll
        for (int nt = 0; nt < 4; nt++) {
            uint32_t bbase = S0 + OF_K + (uint32_t)((n0 + nt * 8 + rq) * 528 + kk * 32 + p4);
            uint32_t bf[2];
            bf[0] = lds32v(bbase);
            bf[1] = lds32v(bbase + 16);
            MMAF16(acc[nt], ah, bf);
            MMAF16(acc[nt], al, bf);
        }
    }
#pragma unroll
    for (int nt = 0; nt < 4; nt++) {
        int r = m0 + rq;
        int c = n0 + nt * 8 + (lane & 3) * 2;
        *(float2*)&smf[(OF_S >> 2) + r * 68 + c]       = make_float2(acc[nt][0] * 0.0625f, acc[nt][1] * 0.0625f);
        *(float2*)&smf[(OF_S >> 2) + (r + 8) * 68 + c] = make_float2(acc[nt][2] * 0.0625f, acc[nt][3] * 0.0625f);
    }
    __syncthreads();

    // ---- softmax over d, write att as fp16 hi/lo ----
    if (tid < 64) {
        float* row = &smf[(OF_S >> 2) + tid * 68];
        float m = row[0];
        for (int d = 1; d < 64; d++) m = fmaxf(m, row[d]);
        float s = 0.f;
        float e[64];
        for (int d = 0; d < 64; d++) { e[d] = __expf(row[d] - m); s += e[d]; }
        float inv = 1.f / s;
        for (int d = 0; d < 64; d += 2) {
            float w0 = e[d] * inv, w1 = e[d + 1] * inv;
            __half h0 = __float2half(w0);
            __half h1 = __float2half(w1);
            __half2 hh; hh.x = h0; hh.y = h1;
            *(__half2*)(smc + OF_AH + tid * 144 + d * 2) = hh;
            __half2 ll;
            ll.x = __float2half(w0 - __half2float(h0));
            ll.y = __float2half(w1 - __half2float(h1));
            *(__half2*)(smc + OF_AL + tid * 144 + d * 2) = ll;
        }
        smf[(OF_S >> 2) + tid] = 0.f;        // GN sum
        smf[(OF_S >> 2) + 64 + tid] = 0.f;   // GN sumsq
    }

    // ---- AV: virt[b][c] = sum_d att[b][d] v[d][c], chunked over c ----
    float gs0 = 0.f, gss0 = 0.f, gs1 = 0.f, gss1 = 0.f;

    for (int cc = 0; cc < 4; cc++) {
        __syncthreads();
        if (cc < 3) {
            int nb = (cc + 1) & 1;
            for (int idx = tid; idx < 512; idx += 256) {
                int d = idx >> 3, ch = idx & 7;
                size_t g = ((size_t)d * NL + l) * NC + (cc + 1) * 64 + ch * 8;
                cpa16(S0 + OF_V + (uint32_t)(nb * 9216 + d * 144 + ch * 16), g_vf + g);
            }
            asm volatile("cp.async.commit_group;" ::: "memory");
            asm volatile("cp.async.wait_group 1;" ::: "memory");
        } else {
            asm volatile("cp.async.wait_group 0;" ::: "memory");
        }
        __syncthreads();

        const uint32_t VB = S0 + OF_V + (uint32_t)((cc & 1) * 9216);

        float av[4][4];
#pragma unroll
        for (int i = 0; i < 4; i++)
#pragma unroll
            for (int j = 0; j < 4; j++) av[i][j] = 0.f;

#pragma unroll
        for (int k = 0; k < 4; k++) {
            uint32_t abase = S0 + (uint32_t)((m0 + rq) * 144 + k * 32 + p4);
            uint32_t ah[4], al[4];
            ah[0] = lds32v(abase + OF_AH);
            ah[1] = lds32v(abase + OF_AH + 8 * 144);
            ah[2] = lds32v(abase + OF_AH + 16);
            ah[3] = lds32v(abase + OF_AH + 8 * 144 + 16);
            al[0] = lds32v(abase + OF_AL);
            al[1] = lds32v(abase + OF_AL + 8 * 144);
            al[2] = lds32v(abase + OF_AL + 16);
            al[3] = lds32v(abase + OF_AL + 8 * 144 + 16);
            int d0 = k * 16 + (lane & 3) * 2;
#pragma unroll
            for (int nt = 0; nt < 4; nt++) {
                int c = n0 + nt * 8 + rq;
                uint32_t a0 = VB + (uint32_t)(d0 * 144 + c * 2);
                uint32_t bf[2];
                bf[0] = lds_u16pair(a0, a0 + 144);
                bf[1] = lds_u16pair(a0 + 8 * 144, a0 + 9 * 144);
                MMAF16(av[nt], ah, bf);
                MMAF16(av[nt], al, bf);
            }
        }
#pragma unroll
        for (int nt = 0; nt < 4; nt++) {
            int b0r = m0 + rq;
            int c = cc * 64 + n0 + nt * 8 + (lane & 3) * 2;
            float2 v01 = make_float2(av[nt][0], av[nt][1]);
            float2 v23 = make_float2(av[nt][2], av[nt][3]);
            *(float2*)(g_virt + ((size_t)b0r * NL + l) * NC + c)       = v01;
            *(float2*)(g_virt + ((size_t)(b0r + 8) * NL + l) * NC + c) = v23;
            gs0  += v01.x + v01.y;
            gss0 += v01.x * v01.x + v01.y * v01.y;
            gs1  += v23.x + v23.y;
            gss1 += v23.x * v23.x + v23.y * v23.y;
        }
    }

    gs0  += __shfl_xor_sync(0xffffffffu, gs0, 1);  gs0  += __shfl_xor_sync(0xffffffffu, gs0, 2);
    gss0 += __shfl_xor_sync(0xffffffffu, gss0, 1); gss0 += __shfl_xor_sync(0xffffffffu, gss0, 2);
    gs1  += __shfl_xor_sync(0xffffffffu, gs1, 1);  gs1  += __shfl_xor_sync(0xffffffffu, gs1, 2);
    gss1 += __shfl_xor_sync(0xffffffffu, gss1, 1); gss1 += __shfl_xor_sync(0xffffffffu, gss1, 2);
    if ((lane & 3) == 0) {
        atomicAdd(&smf[(OF_S >> 2) + m0 + rq], gs0);
        atomicAdd(&smf[(OF_S >> 2) + 64 + m0 + rq], gss0);
        atomicAdd(&smf[(OF_S >> 2) + m0 + rq + 8], gs1);
        atomicAdd(&smf[(OF_S >> 2) + 64 + m0 + rq + 8], gss1);
    }
    __syncthreads();
    if (tid < 64) {
        atomicAdd(&g_psum[tid],   smf[(OF_S >> 2) + tid]);
        atomicAdd(&g_psumsq[tid], smf[(OF_S >> 2) + 64 + tid]);
    }
}

// ================= K: stats =================
__global__ void k_stats()
{
    int b = threadIdx.x;
    if (b < NB) {
        const float n = (float)NC * (float)NL;
        float mean = g_psum[b] / n;
        float var  = g_psumsq[b] / n - mean * mean;
        if (var < 0.f) var = 0.f;
        g_mean[b] = mean;
        g_rstd[b] = rsqrtf(var + 1e-5f);
    }
}

// ================= K: GN+ReLU on virt -> fp16 hi/lo =================
__global__ __launch_bounds__(256) void k_prep2(const float* __restrict__ gamma, const float* __restrict__ beta)
{
    size_t i4 = ((size_t)blockIdx.x * 256 + threadIdx.x) * 4;
    int c = (int)(i4 & 255);
    int b = (int)(i4 >> 20);
    float mean = g_mean[b], rstd = g_rstd[b];
    float4 v = *(const float4*)(g_virt + i4);
    float vv[4] = { v.x, v.y, v.z, v.w };
#pragma unroll
    for (int i = 0; i < 4; i++) {
        float y = fmaxf(fmaf((vv[i] - mean) * rstd, gamma[c + i], beta[c + i]), 0.f);
        __half h = __float2half(y);
        g_nh[i4 + i] = h;
        g_nl[i4 + i] = __float2half(y - __half2float(h));
    }
}

// ================= launch =================
extern "C" void kernel_launch(void* const* d_in, const int* in_sizes, int n_in,
                              void* d_out, int out_size)
{
    const float* x     = (const float*)d_in[0];
    const float* Wq    = (const float*)d_in[1];
    const float* Wk    = (const float*)d_in[2];
    const float* Wv    = (const float*)d_in[3];
    const float* Wc    = (const float*)d_in[4];
    const float* Wout  = (const float*)d_in[5];
    const float* gamma = (const float*)d_in[6];
    const float* beta  = (const float*)d_in[7];
    float* out = (float*)d_out;

    cudaFuncSetAttribute(k_attn,    cudaFuncAttributeMaxDynamicSharedMemorySize, SM_ATTN_BYTES);
    cudaFuncSetAttribute(k_gemm<0>, cudaFuncAttributeMaxDynamicSharedMemorySize, SMEM_GEMM);
    cudaFuncSetAttribute(k_gemm<1>, cudaFuncAttributeMaxDynamicSharedMemorySize, SMEM_GEMM);

    k_zero<<<1, 128>>>();
    k_prep0<<<dim3(64, 4, 64), 256>>>(x);
    k_gmatA<<<16, 256>>>(Wq, Wk);
    k_gmatB<<<16, 256>>>(Wout, Wc);
    k_prepw<<<128, 256>>>(Wv, Wout);
    k_gemm<0><<<dim3(2048, 4), 256, SMEM_GEMM>>>(nullptr);   // z,v (fp16)
    k_attn<<<NL, 256, SM_ATTN_BYTES>>>();
    k_stats<<<1, 64>>>();
    k_prep2<<<65536, 256>>>(gamma, beta);
    k_gemm<1><<<dim3(2048, 2), 256, SMEM_GEMM>>>(out);       // out = Wout x + Wz gn
}

// round 13
// speedup vs baseline: 1.8318x; 1.2005x over previous
#include <cuda_runtime.h>
#include <cuda_fp16.h>
#include <cstdint>

#define NB   64
#define NC   256
#define NL   4096
#define NOUT 256
#define NTOK (NB * NL)   // 262144 tokens

// ================= helpers =================
__device__ __forceinline__ uint32_t smem_to_u32(const void* p) {
    uint32_t a;
    asm("{ .reg .u64 t; cvta.to.shared.u64 t, %1; cvt.u32.u64 %0, t; }" : "=r"(a) : "l"(p));
    return a;
}
__device__ __forceinline__ void cpa16(uint32_t s, const void* g) {
    asm volatile("cp.async.cg.shared.global [%0], [%1], 16;" :: "r"(s), "l"(g) : "memory");
}
__device__ __forceinline__ uint32_t lds32v(uint32_t a) {
    uint32_t v;
    asm volatile("ld.shared.b32 %0, [%1];" : "=r"(v) : "r"(a) : "memory");
    return v;
}
__device__ __forceinline__ uint32_t lds_u16pair(uint32_t a0, uint32_t a1) {
    uint32_t lo, hi;
    asm volatile("ld.shared.u16 %0, [%1];" : "=r"(lo) : "r"(a0) : "memory");
    asm volatile("ld.shared.u16 %0, [%1];" : "=r"(hi) : "r"(a1) : "memory");
    return lo | (hi << 16);
}
#define MMAF16(d, a, b) \
    asm volatile("mma.sync.aligned.m16n8k16.row.col.f32.f16.f16.f32 " \
        "{%0,%1,%2,%3},{%4,%5,%6,%7},{%8,%9},{%0,%1,%2,%3};" \
        : "+f"((d)[0]), "+f"((d)[1]), "+f"((d)[2]), "+f"((d)[3]) \
        : "r"((a)[0]), "r"((a)[1]), "r"((a)[2]), "r"((a)[3]), "r"((b)[0]), "r"((b)[1]))

// ================= scratch (device globals; referenced ONLY in device code) =================
__device__ __align__(256) __half g_xh  [(long long)NTOK * NC];
__device__ __align__(256) __half g_xl  [(long long)NTOK * NC];
__device__ __align__(256) __half g_zf  [(long long)NTOK * NC];
__device__ __align__(256) __half g_vf  [(long long)NTOK * NC];
__device__ __align__(256) float  g_virt[(long long)NTOK * NC];
__device__ __align__(256) __half g_nh  [(long long)NTOK * NC];
__device__ __align__(256) __half g_Gf [NC * NC];
__device__ __align__(256) __half g_wvf[NC * NC];
__device__ __align__(256) __half g_wof[NC * NC];
__device__ __align__(256) __half g_wzf[NC * NC];
__device__ float g_psum[NB], g_psumsq[NB], g_mean[NB], g_rstd[NB];

// ================= K: zero GN accumulators =================
__global__ void k_zero()
{
    int t = threadIdx.x;
    if (t < NB) { g_psum[t] = 0.f; g_psumsq[t] = 0.f; }
}

// ================= K: transpose x -> fp16 hi/lo split (token-major) =================
__global__ __launch_bounds__(256) void k_prep0(const float* __restrict__ x)
{
    __shared__ float tile[64][65];
    const int b  = blockIdx.z;
    const int l0 = blockIdx.x << 6;
    const int c0 = blockIdx.y << 6;
    const int tid = threadIdx.x;
    const int tx = tid & 63, ty = tid >> 6;

    const float* xp = x + (size_t)b * NC * NL + (size_t)c0 * NL + l0;
#pragma unroll
    for (int i = 0; i < 16; i++) {
        int r = i * 4 + ty;
        tile[r][tx] = xp[(size_t)r * NL + tx];
    }
    __syncthreads();
#pragma unroll
    for (int i = 0; i < 16; i++) {
        int lr = i * 4 + ty;
        float v = tile[tx][lr];
        size_t idx = ((size_t)(b * NL + l0 + lr)) * NC + c0 + tx;
        __half h = __float2half(v);
        g_xh[idx] = h;
        g_xl[idx] = __float2half(v - __half2float(h));
    }
}

// ================= K: G[e][f] = sum_o Wq[o][e] Wk[o][f] -> fp16 =================
__global__ __launch_bounds__(256) void k_gmatA(const float* __restrict__ Wq, const float* __restrict__ Wk)
{
    __shared__ float sA[16][68], sB[16][68];
    const int e0 = (blockIdx.x & 3) << 6;
    const int f0 = (blockIdx.x >> 2) << 6;
    const int tid = threadIdx.x;
    const int tx = tid & 15, ty = tid >> 4;

    float acc[4][4];
#pragma unroll
    for (int i = 0; i < 4; i++)
#pragma unroll
        for (int j = 0; j < 4; j++) acc[i][j] = 0.f;

    for (int k0 = 0; k0 < NC; k0 += 16) {
#pragma unroll
        for (int i = 0; i < 4; i++) {
            int r = (tid >> 6) + i * 4, col = tid & 63;
            sA[r][col] = Wq[(size_t)(k0 + r) * NC + e0 + col];
            sB[r][col] = Wk[(size_t)(k0 + r) * NC + f0 + col];
        }
        __syncthreads();
#pragma unroll
        for (int kk = 0; kk < 16; kk++) {
            float a[4], bb[4];
#pragma unroll
            for (int i = 0; i < 4; i++) { a[i] = sA[kk][ty * 4 + i]; bb[i] = sB[kk][tx * 4 + i]; }
#pragma unroll
            for (int i = 0; i < 4; i++)
#pragma unroll
                for (int j = 0; j < 4; j++) acc[i][j] = fmaf(a[i], bb[j], acc[i][j]);
        }
        __syncthreads();
    }
#pragma unroll
    for (int i = 0; i < 4; i++)
#pragma unroll
        for (int j = 0; j < 4; j++)
            g_Gf[(e0 + ty * 4 + i) * NC + f0 + tx * 4 + j] = __float2half(acc[i][j]);
}

// ================= K: Wz[o][c] = sum_m Wout[o][m] Wc[m][c] -> fp16 =================
__global__ __launch_bounds__(256) void k_gmatB(const float* __restrict__ Wo, const float* __restrict__ Wc)
{
    __shared__ float sA[16][68], sB[16][68];
    const int e0 = (blockIdx.x & 3) << 6;      // o tile
    const int f0 = (blockIdx.x >> 2) << 6;     // c tile
    const int tid = threadIdx.x;
    const int tx = tid & 15, ty = tid >> 4;

    float acc[4][4];
#pragma unroll
    for (int i = 0; i < 4; i++)
#pragma unroll
        for (int j = 0; j < 4; j++) acc[i][j] = 0.f;

    for (int k0 = 0; k0 < NC; k0 += 16) {
#pragma unroll
        for (int i = 0; i < 4; i++) {
            int r = (tid >> 6) + i * 4, col = tid & 63;
            sA[r][col] = Wo[(size_t)(e0 + col) * NC + k0 + r];   // transposed gather
            sB[r][col] = Wc[(size_t)(k0 + r) * NC + f0 + col];
        }
        __syncthreads();
#pragma unroll
        for (int kk = 0; kk < 16; kk++) {
            float a[4], bb[4];
#pragma unroll
            for (int i = 0; i < 4; i++) { a[i] = sA[kk][ty * 4 + i]; bb[i] = sB[kk][tx * 4 + i]; }
#pragma unroll
            for (int i = 0; i < 4; i++)
#pragma unroll
                for (int j = 0; j < 4; j++) acc[i][j] = fmaf(a[i], bb[j], acc[i][j]);
        }
        __syncthreads();
    }
#pragma unroll
    for (int i = 0; i < 4; i++)
#pragma unroll
        for (int j = 0; j < 4; j++)
            g_wzf[(e0 + ty * 4 + i) * NC + f0 + tx * 4 + j] = __float2half(acc[i][j]);
}

// ================= K: round Wv, Wout to fp16 =================
__global__ __launch_bounds__(256) void k_prepw(
    const float* __restrict__ Wv, const float* __restrict__ Wo)
{
    int gid = blockIdx.x * 256 + threadIdx.x;
    int arr = gid >> 14;
    int off = (gid & 16383) * 4;
    const float* src = (arr == 0) ? Wv : Wo;
    __half* dst = (arr == 0) ? g_wvf : g_wof;
    float4 v = *(const float4*)(src + off);
    __half2 h0; h0.x = __float2half(v.x); h0.y = __float2half(v.y);
    __half2 h1; h1.x = __float2half(v.z); h1.y = __float2half(v.w);
    *(__half2*)(dst + off)     = h0;
    *(__half2*)(dst + off + 2) = h1;
}

// ================= K: fp16 GEMM, 4-stage pipeline =================
// KIND 0: grid (2048, 4): y<2 -> z = G x (A split hi/lo, 2 MMAs/tile);
//                         y>=2 -> v = Wv x (A single fp16, 1 MMA/tile)
//         A row 80B [hi k0-7|hi k8-15|lo k0-7|lo k8-15|pad]; W row 48B.
// KIND 1: grid (2048, 2): out = Wout x + Wz gn (K=512, A single fp16)
//         A row 48B; W row 48B. Transposed fp32 store.
#define WROWB   48
#define A0ROWB  80
#define A1ROWB  48
#define STB0    (128 * A0ROWB + 128 * WROWB)   // 16384
#define STB1    (128 * A1ROWB + 128 * WROWB)   // 12288
#define NPIPE   4
#define SMEM_GEMM0 (NPIPE * STB0)   // 65536
#define SMEM_GEMM1 (NPIPE * STB1)   // 49152

template<int KIND>
__global__ __launch_bounds__(256) void k_gemm(float* __restrict__ outf)
{
    extern __shared__ __align__(128) char smem[];
    const uint32_t sbase = smem_to_u32(smem);
    const int tid  = threadIdx.x;
    const int wid  = tid >> 5;
    const int lane = tid & 31;
    const int t0   = blockIdx.x << 7;
    const int NS   = (KIND == 0) ? 16 : 32;
    constexpr int AR  = (KIND == 0) ? A0ROWB : A1ROWB;
    constexpr int STB = (KIND == 0) ? STB0 : STB1;
    constexpr uint32_t HALF = 128u * (uint32_t)AR;

    int o0, wsel = 0;
    if (KIND == 0) { wsel = blockIdx.y >> 1; o0 = (blockIdx.y & 1) << 7; }
    else           { o0 = blockIdx.y << 7; }

    const int wm = wid & 1;
    const int wn = wid >> 1;

    auto load_stage = [&](int s) {
        const __half *Ah, *Al, *Wf;
        int k0;
        if (KIND == 0) {
            Ah = g_xh; Al = g_xl;
            Wf = wsel ? g_wvf : g_Gf;
            k0 = s << 4;
        } else {
            Al = nullptr;
            if (s < 16) { Ah = g_xh; Wf = g_wof; k0 = s << 4; }
            else        { Ah = g_nh; Wf = g_wzf; k0 = (s - 16) << 4; }
        }
        const uint32_t buf = sbase + (uint32_t)(s & (NPIPE - 1)) * (uint32_t)STB;
        if (KIND == 0) {
#pragma unroll
            for (int i = 0; i < 3; i++) {
                int idx = tid + (i << 8);          // [0,768)
                if (idx < 512) {
                    int r = idx >> 2, ch = idx & 3;
                    if (!(wsel && ch >= 2)) {      // v: skip lo chunks
                        const __half* src = ((ch < 2) ? Ah : Al) + (size_t)(t0 + r) * NC + k0 + ((ch & 1) << 3);
                        cpa16(buf + (uint32_t)(r * AR + (ch << 4)), src);
                    }
                } else {
                    int j = idx - 512;
                    int r = j >> 1, ch = j & 1;
                    const __half* src = Wf + (size_t)(o0 + r) * NC + k0 + (ch << 3);
                    cpa16(buf + HALF + (uint32_t)(r * WROWB + (ch << 4)), src);
                }
            }
        } else {
#pragma unroll
            for (int i = 0; i < 2; i++) {
                int idx = tid + (i << 8);          // [0,512)
                if (idx < 256) {
                    int r = idx >> 1, ch = idx & 1;
                    const __half* src = Ah + (size_t)(t0 + r) * NC + k0 + (ch << 3);
                    cpa16(buf + (uint32_t)(r * AR + (ch << 4)), src);
                } else {
                    int j = idx - 256;
                    int r = j >> 1, ch = j & 1;
                    const __half* src = Wf + (size_t)(o0 + r) * NC + k0 + (ch << 3);
                    cpa16(buf + HALF + (uint32_t)(r * WROWB + (ch << 4)), src);
                }
            }
        }
        asm volatile("cp.async.commit_group;" ::: "memory");
    };

    float acc[4][4][4];
#pragma unroll
    for (int a = 0; a < 4; a++)
#pragma unroll
        for (int b = 0; b < 4; b++)
#pragma unroll
            for (int c = 0; c < 4; c++) acc[a][b][c] = 0.f;

    const int rq = lane >> 2;
    const int p4 = (lane & 3) << 2;

    load_stage(0);
    load_stage(1);
    load_stage(2);

    for (int s = 0; s < NS; s++) {
        int rem = NS - 1 - s;
        if (rem >= 2)      asm volatile("cp.async.wait_group 2;" ::: "memory");
        else if (rem == 1) asm volatile("cp.async.wait_group 1;" ::: "memory");
        else               asm volatile("cp.async.wait_group 0;" ::: "memory");
        __syncthreads();
        if (s + 3 < NS) load_stage(s + 3);

        const uint32_t bufA = sbase + (uint32_t)(s & (NPIPE - 1)) * (uint32_t)STB;
        const uint32_t bufW = bufA + HALF;

        uint32_t ah[4][4], al[4][4], bf[4][2];
#pragma unroll
        for (int mt = 0; mt < 4; mt++) {
            uint32_t base = bufA + (uint32_t)((wm * 64 + mt * 16 + rq) * AR + p4);
            ah[mt][0] = lds32v(base);
            ah[mt][1] = lds32v(base + 8 * AR);
            ah[mt][2] = lds32v(base + 16);
            ah[mt][3] = lds32v(base + 8 * AR + 16);
            if (KIND == 0 && !wsel) {
                al[mt][0] = lds32v(base + 32);
                al[mt][1] = lds32v(base + 8 * AR + 32);
                al[mt][2] = lds32v(base + 48);
                al[mt][3] = lds32v(base + 8 * AR + 48);
            }
        }
#pragma unroll
        for (int nt = 0; nt < 4; nt++) {
            uint32_t base = bufW + (uint32_t)((wn * 32 + nt * 8 + rq) * WROWB + p4);
            bf[nt][0] = lds32v(base);
            bf[nt][1] = lds32v(base + 16);
        }
#pragma unroll
        for (int mt = 0; mt < 4; mt++)
#pragma unroll
            for (int nt = 0; nt < 4; nt++) {
                MMAF16(acc[mt][nt], ah[mt], bf[nt]);
                if (KIND == 0 && !wsel) MMAF16(acc[mt][nt], al[mt], bf[nt]);
            }
    }

    // epilogue
    const int fr = lane >> 2;
    const int fc = (lane & 3) * 2;
#pragma unroll
    for (int mt = 0; mt < 4; mt++) {
#pragma unroll
        for (int nt = 0; nt < 4; nt++) {
            int r = wm * 64 + mt * 16 + fr;
            int c = wn * 32 + nt * 8 + fc;
            float d0 = acc[mt][nt][0], d1 = acc[mt][nt][1];
            float d2 = acc[mt][nt][2], d3 = acc[mt][nt][3];
            if (KIND == 0) {
                __half* dst = wsel ? g_vf : g_zf;
                __half2 h01; h01.x = __float2half(d0); h01.y = __float2half(d1);
                __half2 h23; h23.x = __float2half(d2); h23.y = __float2half(d3);
                *(__half2*)(dst + (size_t)(t0 + r) * NC + o0 + c)     = h01;
                *(__half2*)(dst + (size_t)(t0 + r + 8) * NC + o0 + c) = h23;
            } else {
                const int b = t0 >> 12;
                int l = (t0 & 4095) + r;
                outf[((size_t)(b * NOUT + o0 + c))     * NL + l] = d0;
                outf[((size_t)(b * NOUT + o0 + c + 1)) * NL + l] = d1;
                outf[((size_t)(b * NOUT + o0 + c))     * NL + l + 8] = d2;
                outf[((size_t)(b * NOUT + o0 + c + 1)) * NL + l + 8] = d3;
            }
        }
    }
}

// ================= K: tensorized per-l batch attention + GN partials =================
// smem bytes: QH 0 (64x528), QL 33792, K 67584 (64x528, single fp16),
//   S 101376 (fp32 [64][68], reused as GN accum), AH 118784 (64x144),
//   AL 128000, V 137216 (2 x 64x144 single fp16)
#define OF_QH 0
#define OF_QL 33792
#define OF_K  67584
#define OF_S  101376
#define OF_AH 118784
#define OF_AL 128000
#define OF_V  137216
#define SM_ATTN_BYTES (OF_V + 2 * 9216)   // 155648

__global__ __launch_bounds__(256) void k_attn()
{
    extern __shared__ __align__(128) char smc[];
    const uint32_t S0 = smem_to_u32(smc);
    float* smf = (float*)smc;
    const int l = blockIdx.x;
    const int tid = threadIdx.x;
    const int wid = tid >> 5, lane = tid & 31;
    const int rq = lane >> 2, p4 = (lane & 3) << 2;
    const int m0 = (wid & 3) * 16;
    const int n0 = (wid >> 2) * 32;

    // ---- load Q(x hi/lo) and K(z single) ----
    for (int idx = tid; idx < 2048; idx += 256) {
        int row = idx >> 5, ch = idx & 31;
        size_t g = ((size_t)row * NL + l) * NC + ch * 8;
        uint32_t so = (uint32_t)(row * 528 + ch * 16);
        cpa16(S0 + OF_QH + so, g_xh + g);
        cpa16(S0 + OF_QL + so, g_xl + g);
        cpa16(S0 + OF_K  + so, g_zf + g);
    }
    // V chunk 0 into buffer 0
    for (int idx = tid; idx < 512; idx += 256) {
        int d = idx >> 3, ch = idx & 7;
        size_t g = ((size_t)d * NL + l) * NC + ch * 8;
        cpa16(S0 + OF_V + (uint32_t)(d * 144 + ch * 16), g_vf + g);
    }
    asm volatile("cp.async.commit_group;" ::: "memory");
    asm volatile("cp.async.wait_group 0;" ::: "memory");
    __syncthreads();

    // ---- scores S[b][d] = (x_b . z_d)/16 ; 2-term one-sided split ----
    float acc[4][4];
#pragma unroll
    for (int i = 0; i < 4; i++)
#pragma unroll
        for (int j = 0; j < 4; j++) acc[i][j] = 0.f;

#pragma unroll
    for (int kk = 0; kk < 16; kk++) {
        uint32_t abase = S0 + (uint32_t)((m0 + rq) * 528 + kk * 32 + p4);
        uint32_t ah[4], al[4];
        ah[0] = lds32v(abase + OF_QH);
        ah[1] = lds32v(abase + OF_QH + 8 * 528);
        ah[2] = lds32v(abase + OF_QH + 16);
        ah[3] = lds32v(abase + OF_QH + 8 * 528 + 16);
        al[0] = lds32v(abase + OF_QL);
        al[1] = lds32v(abase + OF_QL + 8 * 528);
        al[2] = lds32v(abase + OF_QL + 16);
        al[3] = lds32v(abase + OF_QL + 8 * 528 + 16);
#pragma unroll
        for (int nt = 0; nt < 4; nt++) {
            uint32_t bbase = S0 + OF_K + (uint32_t)((n0 + nt * 8 + rq) * 528 + kk * 32 + p4);
            uint32_t bf[2];
            bf[0] = lds32v(bbase);
            bf[1] = lds32v(bbase + 16);
            MMAF16(acc[nt], ah, bf);
            MMAF16(acc[nt], al, bf);
        }
    }
#pragma unroll
    for (int nt = 0; nt < 4; nt++) {
        int r = m0 + rq;
        int c = n0 + nt * 8 + (lane & 3) * 2;
        *(float2*)&smf[(OF_S >> 2) + r * 68 + c]       = make_float2(acc[nt][0] * 0.0625f, acc[nt][1] * 0.0625f);
        *(float2*)&smf[(OF_S >> 2) + (r + 8) * 68 + c] = make_float2(acc[nt][2] * 0.0625f, acc[nt][3] * 0.0625f);
    }
    __syncthreads();

    // ---- softmax over d, write att as fp16 hi/lo ----
    if (tid < 64) {
        float* row = &smf[(OF_S >> 2) + tid * 68];
        float m = row[0];
        for (int d = 1; d < 64; d++) m = fmaxf(m, row[d]);
        float s = 0.f;
        float e[64];
        for (int d = 0; d < 64; d++) { e[d] = __expf(row[d] - m); s += e[d]; }
        float inv = 1.f / s;
        for (int d = 0; d < 64; d += 2) {
            float w0 = e[d] * inv, w1 = e[d + 1] * inv;
            __half h0 = __float2half(w0);
            __half h1 = __float2half(w1);
            __half2 hh; hh.x = h0; hh.y = h1;
            *(__half2*)(smc + OF_AH + tid * 144 + d * 2) = hh;
            __half2 ll;
            ll.x = __float2half(w0 - __half2float(h0));
            ll.y = __float2half(w1 - __half2float(h1));
            *(__half2*)(smc + OF_AL + tid * 144 + d * 2) = ll;
        }
        smf[(OF_S >> 2) + tid] = 0.f;        // GN sum
        smf[(OF_S >> 2) + 64 + tid] = 0.f;   // GN sumsq
    }

    // ---- AV: virt[b][c] = sum_d att[b][d] v[d][c], chunked over c ----
    float gs0 = 0.f, gss0 = 0.f, gs1 = 0.f, gss1 = 0.f;

    for (int cc = 0; cc < 4; cc++) {
        __syncthreads();
        if (cc < 3) {
            int nb = (cc + 1) & 1;
            for (int idx = tid; idx < 512; idx += 256) {
                int d = idx >> 3, ch = idx & 7;
                size_t g = ((size_t)d * NL + l) * NC + (cc + 1) * 64 + ch * 8;
                cpa16(S0 + OF_V + (uint32_t)(nb * 9216 + d * 144 + ch * 16), g_vf + g);
            }
            asm volatile("cp.async.commit_group;" ::: "memory");
            asm volatile("cp.async.wait_group 1;" ::: "memory");
        } else {
            asm volatile("cp.async.wait_group 0;" ::: "memory");
        }
        __syncthreads();

        const uint32_t VB = S0 + OF_V + (uint32_t)((cc & 1) * 9216);

        float av[4][4];
#pragma unroll
        for (int i = 0; i < 4; i++)
#pragma unroll
            for (int j = 0; j < 4; j++) av[i][j] = 0.f;

#pragma unroll
        for (int k = 0; k < 4; k++) {
            uint32_t abase = S0 + (uint32_t)((m0 + rq) * 144 + k * 32 + p4);
            uint32_t ah[4], al[4];
            ah[0] = lds32v(abase + OF_AH);
            ah[1] = lds32v(abase + OF_AH + 8 * 144);
            ah[2] = lds32v(abase + OF_AH + 16);
            ah[3] = lds32v(abase + OF_AH + 8 * 144 + 16);
            al[0] = lds32v(abase + OF_AL);
            al[1] = lds32v(abase + OF_AL + 8 * 144);
            al[2] = lds32v(abase + OF_AL + 16);
            al[3] = lds32v(abase + OF_AL + 8 * 144 + 16);
            int d0 = k * 16 + (lane & 3) * 2;
#pragma unroll
            for (int nt = 0; nt < 4; nt++) {
                int c = n0 + nt * 8 + rq;
                uint32_t a0 = VB + (uint32_t)(d0 * 144 + c * 2);
                uint32_t bf[2];
                bf[0] = lds_u16pair(a0, a0 + 144);
                bf[1] = lds_u16pair(a0 + 8 * 144, a0 + 9 * 144);
                MMAF16(av[nt], ah, bf);
                MMAF16(av[nt], al, bf);
            }
        }
#pragma unroll
        for (int nt = 0; nt < 4; nt++) {
            int b0r = m0 + rq;
            int c = cc * 64 + n0 + nt * 8 + (lane & 3) * 2;
            float2 v01 = make_float2(av[nt][0], av[nt][1]);
            float2 v23 = make_float2(av[nt][2], av[nt][3]);
            *(float2*)(g_virt + ((size_t)b0r * NL + l) * NC + c)       = v01;
            *(float2*)(g_virt + ((size_t)(b0r + 8) * NL + l) * NC + c) = v23;
            gs0  += v01.x + v01.y;
            gss0 += v01.x * v01.x + v01.y * v01.y;
            gs1  += v23.x + v23.y;
            gss1 += v23.x * v23.x + v23.y * v23.y;
        }
    }

    gs0  += __shfl_xor_sync(0xffffffffu, gs0, 1);  gs0  += __shfl_xor_sync(0xffffffffu, gs0, 2);
    gss0 += __shfl_xor_sync(0xffffffffu, gss0, 1); gss0 += __shfl_xor_sync(0xffffffffu, gss0, 2);
    gs1  += __shfl_xor_sync(0xffffffffu, gs1, 1);  gs1  += __shfl_xor_sync(0xffffffffu, gs1, 2);
    gss1 += __shfl_xor_sync(0xffffffffu, gss1, 1); gss1 += __shfl_xor_sync(0xffffffffu, gss1, 2);
    if ((lane & 3) == 0) {
        atomicAdd(&smf[(OF_S >> 2) + m0 + rq], gs0);
        atomicAdd(&smf[(OF_S >> 2) + 64 + m0 + rq], gss0);
        atomicAdd(&smf[(OF_S >> 2) + m0 + rq + 8], gs1);
        atomicAdd(&smf[(OF_S >> 2) + 64 + m0 + rq + 8], gss1);
    }
    __syncthreads();
    if (tid < 64) {
        atomicAdd(&g_psum[tid],   smf[(OF_S >> 2) + tid]);
        atomicAdd(&g_psumsq[tid], smf[(OF_S >> 2) + 64 + tid]);
    }
}

// ================= K: stats =================
__global__ void k_stats()
{
    int b = threadIdx.x;
    if (b < NB) {
        const float n = (float)NC * (float)NL;
        float mean = g_psum[b] / n;
        float var  = g_psumsq[b] / n - mean * mean;
        if (var < 0.f) var = 0.f;
        g_mean[b] = mean;
        g_rstd[b] = rsqrtf(var + 1e-5f);
    }
}

// ================= K: GN+ReLU on virt -> single fp16 =================
__global__ __launch_bounds__(256) void k_prep2(const float* __restrict__ gamma, const float* __restrict__ beta)
{
    size_t i4 = ((size_t)blockIdx.x * 256 + threadIdx.x) * 4;
    int c = (int)(i4 & 255);
    int b = (int)(i4 >> 20);
    float mean = g_mean[b], rstd = g_rstd[b];
    float4 v = *(const float4*)(g_virt + i4);
    float vv[4] = { v.x, v.y, v.z, v.w };
    __half2 h0, h1;
    h0.x = __float2half(fmaxf(fmaf((vv[0] - mean) * rstd, gamma[c + 0], beta[c + 0]), 0.f));
    h0.y = __float2half(fmaxf(fmaf((vv[1] - mean) * rstd, gamma[c + 1], beta[c + 1]), 0.f));
    h1.x = __float2half(fmaxf(fmaf((vv[2] - mean) * rstd, gamma[c + 2], beta[c + 2]), 0.f));
    h1.y = __float2half(fmaxf(fmaf((vv[3] - mean) * rstd, gamma[c + 3], beta[c + 3]), 0.f));
    *(__half2*)(g_nh + i4)     = h0;
    *(__half2*)(g_nh + i4 + 2) = h1;
}

// ================= launch =================
extern "C" void kernel_launch(void* const* d_in, const int* in_sizes, int n_in,
                              void* d_out, int out_size)
{
    const float* x     = (const float*)d_in[0];
    const float* Wq    = (const float*)d_in[1];
    const float* Wk    = (const float*)d_in[2];
    const float* Wv    = (const float*)d_in[3];
    const float* Wc    = (const float*)d_in[4];
    const float* Wout  = (const float*)d_in[5];
    const float* gamma = (const float*)d_in[6];
    const float* beta  = (const float*)d_in[7];
    float* out = (float*)d_out;

    cudaFuncSetAttribute(k_attn,    cudaFuncAttributeMaxDynamicSharedMemorySize, SM_ATTN_BYTES);
    cudaFuncSetAttribute(k_gemm<0>, cudaFuncAttributeMaxDynamicSharedMemorySize, SMEM_GEMM0);
    cudaFuncSetAttribute(k_gemm<1>, cudaFuncAttributeMaxDynamicSharedMemorySize, SMEM_GEMM1);

    k_zero<<<1, 128>>>();
    k_prep0<<<dim3(64, 4, 64), 256>>>(x);
    k_gmatA<<<16, 256>>>(Wq, Wk);
    k_gmatB<<<16, 256>>>(Wout, Wc);
    k_prepw<<<128, 256>>>(Wv, Wout);
    k_gemm<0><<<dim3(2048, 4), 256, SMEM_GEMM0>>>(nullptr);   // z (split), v (single)
    k_attn<<<NL, 256, SM_ATTN_BYTES>>>();
    k_stats<<<1, 64>>>();
    k_prep2<<<65536, 256>>>(gamma, beta);
    k_gemm<1><<<dim3(2048, 2), 256, SMEM_GEMM1>>>(out);       // out = Wout x + Wz gn (single-A)
}

// round 14
// speedup vs baseline: 1.8676x; 1.0195x over previous
#include <cuda_runtime.h>
#include <cuda_fp16.h>
#include <cstdint>

#define NB   64
#define NC   256
#define NL   4096
#define NOUT 256
#define NTOK (NB * NL)   // 262144 tokens

// ================= helpers =================
__device__ __forceinline__ uint32_t smem_to_u32(const void* p) {
    uint32_t a;
    asm("{ .reg .u64 t; cvta.to.shared.u64 t, %1; cvt.u32.u64 %0, t; }" : "=r"(a) : "l"(p));
    return a;
}
__device__ __forceinline__ void cpa16(uint32_t s, const void* g) {
    asm volatile("cp.async.cg.shared.global [%0], [%1], 16;" :: "r"(s), "l"(g) : "memory");
}
__device__ __forceinline__ uint32_t lds32v(uint32_t a) {
    uint32_t v;
    asm volatile("ld.shared.b32 %0, [%1];" : "=r"(v) : "r"(a) : "memory");
    return v;
}
__device__ __forceinline__ uint32_t lds_u16pair(uint32_t a0, uint32_t a1) {
    uint32_t lo, hi;
    asm volatile("ld.shared.u16 %0, [%1];" : "=r"(lo) : "r"(a0) : "memory");
    asm volatile("ld.shared.u16 %0, [%1];" : "=r"(hi) : "r"(a1) : "memory");
    return lo | (hi << 16);
}
#define MMAF16(d, a, b) \
    asm volatile("mma.sync.aligned.m16n8k16.row.col.f32.f16.f16.f32 " \
        "{%0,%1,%2,%3},{%4,%5,%6,%7},{%8,%9},{%0,%1,%2,%3};" \
        : "+f"((d)[0]), "+f"((d)[1]), "+f"((d)[2]), "+f"((d)[3]) \
        : "r"((a)[0]), "r"((a)[1]), "r"((a)[2]), "r"((a)[3]), "r"((b)[0]), "r"((b)[1]))

// ================= scratch (device globals; referenced ONLY in device code) =================
__device__ __align__(256) __half g_xh  [(long long)NTOK * NC];
__device__ __align__(256) __half g_xl  [(long long)NTOK * NC];
__device__ __align__(256) __half g_zf  [(long long)NTOK * NC];
__device__ __align__(256) __half g_vf  [(long long)NTOK * NC];
__device__ __align__(256) __half g_vtf [(long long)NTOK * NC];   // virt (fp16)
__device__ __align__(256) __half g_nh  [(long long)NTOK * NC];
__device__ __align__(256) __half g_Gf [NC * NC];
__device__ __align__(256) __half g_wvf[NC * NC];
__device__ __align__(256) __half g_wof[NC * NC];
__device__ __align__(256) __half g_wzf[NC * NC];
__device__ float g_psum[NB], g_psumsq[NB], g_mean[NB], g_rstd[NB];

// ================= K: fused weight prep =================
// blocks 0-15: G = Wq^T Wk -> g_Gf ; 16-31: Wz = Wout*Wc -> g_wzf ;
// 32-159: round Wv/Wout -> g_wvf/g_wof ; 160: zero GN accumulators.
__global__ __launch_bounds__(256) void k_wprep(
    const float* __restrict__ Wq, const float* __restrict__ Wk,
    const float* __restrict__ Wo, const float* __restrict__ Wc,
    const float* __restrict__ Wv)
{
    const int bx = blockIdx.x;
    const int tid = threadIdx.x;

    if (bx >= 160) {
        if (tid < NB) { g_psum[tid] = 0.f; g_psumsq[tid] = 0.f; }
        return;
    }
    if (bx >= 32) {
        int gid = (bx - 32) * 256 + tid;
        int arr = gid >> 14;
        int off = (gid & 16383) * 4;
        const float* src = (arr == 0) ? Wv : Wo;
        __half* dst = (arr == 0) ? g_wvf : g_wof;
        float4 v = *(const float4*)(src + off);
        __half2 h0; h0.x = __float2half(v.x); h0.y = __float2half(v.y);
        __half2 h1; h1.x = __float2half(v.z); h1.y = __float2half(v.w);
        *(__half2*)(dst + off)     = h0;
        *(__half2*)(dst + off + 2) = h1;
        return;
    }

    // GEMM-type prep: bx<16 -> G = Wq^T Wk; else Wz = Wout*Wc
    __shared__ float sA[16][68], sB[16][68];
    const bool isG = (bx < 16);
    const int bb = isG ? bx : bx - 16;
    const int e0 = (bb & 3) << 6;
    const int f0 = (bb >> 2) << 6;
    const int tx = tid & 15, ty = tid >> 4;

    float acc[4][4];
#pragma unroll
    for (int i = 0; i < 4; i++)
#pragma unroll
        for (int j = 0; j < 4; j++) acc[i][j] = 0.f;

    for (int k0 = 0; k0 < NC; k0 += 16) {
#pragma unroll
        for (int i = 0; i < 4; i++) {
            int r = (tid >> 6) + i * 4, col = tid & 63;
            if (isG) {
                sA[r][col] = Wq[(size_t)(k0 + r) * NC + e0 + col];
                sB[r][col] = Wk[(size_t)(k0 + r) * NC + f0 + col];
            } else {
                sA[r][col] = Wo[(size_t)(e0 + col) * NC + k0 + r];
                sB[r][col] = Wc[(size_t)(k0 + r) * NC + f0 + col];
            }
        }
        __syncthreads();
#pragma unroll
        for (int kk = 0; kk < 16; kk++) {
            float a[4], b2[4];
#pragma unroll
            for (int i = 0; i < 4; i++) { a[i] = sA[kk][ty * 4 + i]; b2[i] = sB[kk][tx * 4 + i]; }
#pragma unroll
            for (int i = 0; i < 4; i++)
#pragma unroll
                for (int j = 0; j < 4; j++) acc[i][j] = fmaf(a[i], b2[j], acc[i][j]);
        }
        __syncthreads();
    }
    __half* dst = isG ? g_Gf : g_wzf;
#pragma unroll
    for (int i = 0; i < 4; i++)
#pragma unroll
        for (int j = 0; j < 4; j++)
            dst[(e0 + ty * 4 + i) * NC + f0 + tx * 4 + j] = __float2half(acc[i][j]);
}

// ================= K: transpose x -> fp16 hi/lo split (token-major) =================
__global__ __launch_bounds__(256) void k_prep0(const float* __restrict__ x)
{
    __shared__ float tile[64][65];
    const int b  = blockIdx.z;
    const int l0 = blockIdx.x << 6;
    const int c0 = blockIdx.y << 6;
    const int tid = threadIdx.x;
    const int tx = tid & 63, ty = tid >> 6;

    const float* xp = x + (size_t)b * NC * NL + (size_t)c0 * NL + l0;
#pragma unroll
    for (int i = 0; i < 16; i++) {
        int r = i * 4 + ty;
        tile[r][tx] = xp[(size_t)r * NL + tx];
    }
    __syncthreads();
#pragma unroll
    for (int i = 0; i < 16; i++) {
        int lr = i * 4 + ty;
        float v = tile[tx][lr];
        size_t idx = ((size_t)(b * NL + l0 + lr)) * NC + c0 + tx;
        __half h = __float2half(v);
        g_xh[idx] = h;
        g_xl[idx] = __float2half(v - __half2float(h));
    }
}

// ================= K: fp16 GEMM, 4-stage pipeline =================
// KIND 0: grid (2048, 4): y<2 -> z = G x (A split hi/lo); y>=2 -> v = Wv x (single)
// KIND 1: grid (2048, 2): out = Wout x + Wz gn (K=512, single-A, transposed store)
#define WROWB   48
#define A0ROWB  80
#define A1ROWB  48
#define STB0    (128 * A0ROWB + 128 * WROWB)   // 16384
#define STB1    (128 * A1ROWB + 128 * WROWB)   // 12288
#define NPIPE   4
#define SMEM_GEMM0 (NPIPE * STB0)   // 65536
#define SMEM_GEMM1 (NPIPE * STB1)   // 49152

template<int KIND>
__global__ __launch_bounds__(256) void k_gemm(float* __restrict__ outf)
{
    extern __shared__ __align__(128) char smem[];
    const uint32_t sbase = smem_to_u32(smem);
    const int tid  = threadIdx.x;
    const int wid  = tid >> 5;
    const int lane = tid & 31;
    const int t0   = blockIdx.x << 7;
    const int NS   = (KIND == 0) ? 16 : 32;
    constexpr int AR  = (KIND == 0) ? A0ROWB : A1ROWB;
    constexpr int STB = (KIND == 0) ? STB0 : STB1;
    constexpr uint32_t HALF = 128u * (uint32_t)AR;

    int o0, wsel = 0;
    if (KIND == 0) { wsel = blockIdx.y >> 1; o0 = (blockIdx.y & 1) << 7; }
    else           { o0 = blockIdx.y << 7; }

    const int wm = wid & 1;
    const int wn = wid >> 1;

    auto load_stage = [&](int s) {
        const __half *Ah, *Al, *Wf;
        int k0;
        if (KIND == 0) {
            Ah = g_xh; Al = g_xl;
            Wf = wsel ? g_wvf : g_Gf;
            k0 = s << 4;
        } else {
            Al = nullptr;
            if (s < 16) { Ah = g_xh; Wf = g_wof; k0 = s << 4; }
            else        { Ah = g_nh; Wf = g_wzf; k0 = (s - 16) << 4; }
        }
        const uint32_t buf = sbase + (uint32_t)(s & (NPIPE - 1)) * (uint32_t)STB;
        if (KIND == 0) {
#pragma unroll
            for (int i = 0; i < 3; i++) {
                int idx = tid + (i << 8);          // [0,768)
                if (idx < 512) {
                    int r = idx >> 2, ch = idx & 3;
                    if (!(wsel && ch >= 2)) {      // v: skip lo chunks
                        const __half* src = ((ch < 2) ? Ah : Al) + (size_t)(t0 + r) * NC + k0 + ((ch & 1) << 3);
                        cpa16(buf + (uint32_t)(r * AR + (ch << 4)), src);
                    }
                } else {
                    int j = idx - 512;
                    int r = j >> 1, ch = j & 1;
                    const __half* src = Wf + (size_t)(o0 + r) * NC + k0 + (ch << 3);
                    cpa16(buf + HALF + (uint32_t)(r * WROWB + (ch << 4)), src);
                }
            }
        } else {
#pragma unroll
            for (int i = 0; i < 2; i++) {
                int idx = tid + (i << 8);          // [0,512)
                if (idx < 256) {
                    int r = idx >> 1, ch = idx & 1;
                    const __half* src = Ah + (size_t)(t0 + r) * NC + k0 + (ch << 3);
                    cpa16(buf + (uint32_t)(r * AR + (ch << 4)), src);
                } else {
                    int j = idx - 256;
                    int r = j >> 1, ch = j & 1;
                    const __half* src = Wf + (size_t)(o0 + r) * NC + k0 + (ch << 3);
                    cpa16(buf + HALF + (uint32_t)(r * WROWB + (ch << 4)), src);
                }
            }
        }
        asm volatile("cp.async.commit_group;" ::: "memory");
    };

    float acc[4][4][4];
#pragma unroll
    for (int a = 0; a < 4; a++)
#pragma unroll
        for (int b = 0; b < 4; b++)
#pragma unroll
            for (int c = 0; c < 4; c++) acc[a][b][c] = 0.f;

    const int rq = lane >> 2;
    const int p4 = (lane & 3) << 2;

    load_stage(0);
    load_stage(1);
    load_stage(2);

    for (int s = 0; s < NS; s++) {
        int rem = NS - 1 - s;
        if (rem >= 2)      asm volatile("cp.async.wait_group 2;" ::: "memory");
        else if (rem == 1) asm volatile("cp.async.wait_group 1;" ::: "memory");
        else               asm volatile("cp.async.wait_group 0;" ::: "memory");
        __syncthreads();
        if (s + 3 < NS) load_stage(s + 3);

        const uint32_t bufA = sbase + (uint32_t)(s & (NPIPE - 1)) * (uint32_t)STB;
        const uint32_t bufW = bufA + HALF;

        uint32_t ah[4][4], al[4][4], bf[4][2];
#pragma unroll
        for (int mt = 0; mt < 4; mt++) {
            uint32_t base = bufA + (uint32_t)((wm * 64 + mt * 16 + rq) * AR + p4);
            ah[mt][0] = lds32v(base);
            ah[mt][1] = lds32v(base + 8 * AR);
            ah[mt][2] = lds32v(base + 16);
            ah[mt][3] = lds32v(base + 8 * AR + 16);
            if (KIND == 0 && !wsel) {
                al[mt][0] = lds32v(base + 32);
                al[mt][1] = lds32v(base + 8 * AR + 32);
                al[mt][2] = lds32v(base + 48);
                al[mt][3] = lds32v(base + 8 * AR + 48);
            }
        }
#pragma unroll
        for (int nt = 0; nt < 4; nt++) {
            uint32_t base = bufW + (uint32_t)((wn * 32 + nt * 8 + rq) * WROWB + p4);
            bf[nt][0] = lds32v(base);
            bf[nt][1] = lds32v(base + 16);
        }
#pragma unroll
        for (int mt = 0; mt < 4; mt++)
#pragma unroll
            for (int nt = 0; nt < 4; nt++) {
                MMAF16(acc[mt][nt], ah[mt], bf[nt]);
                if (KIND == 0 && !wsel) MMAF16(acc[mt][nt], al[mt], bf[nt]);
            }
    }

    // epilogue
    const int fr = lane >> 2;
    const int fc = (lane & 3) * 2;
#pragma unroll
    for (int mt = 0; mt < 4; mt++) {
#pragma unroll
        for (int nt = 0; nt < 4; nt++) {
            int r = wm * 64 + mt * 16 + fr;
            int c = wn * 32 + nt * 8 + fc;
            float d0 = acc[mt][nt][0], d1 = acc[mt][nt][1];
            float d2 = acc[mt][nt][2], d3 = acc[mt][nt][3];
            if (KIND == 0) {
                __half* dst = wsel ? g_vf : g_zf;
                __half2 h01; h01.x = __float2half(d0); h01.y = __float2half(d1);
                __half2 h23; h23.x = __float2half(d2); h23.y = __float2half(d3);
                *(__half2*)(dst + (size_t)(t0 + r) * NC + o0 + c)     = h01;
                *(__half2*)(dst + (size_t)(t0 + r + 8) * NC + o0 + c) = h23;
            } else {
                const int b = t0 >> 12;
                int l = (t0 & 4095) + r;
                outf[((size_t)(b * NOUT + o0 + c))     * NL + l] = d0;
                outf[((size_t)(b * NOUT + o0 + c + 1)) * NL + l] = d1;
                outf[((size_t)(b * NOUT + o0 + c))     * NL + l + 8] = d2;
                outf[((size_t)(b * NOUT + o0 + c + 1)) * NL + l + 8] = d3;
            }
        }
    }
}

// ================= K: tensorized per-l batch attention + GN partials =================
#define OF_QH 0
#define OF_QL 33792
#define OF_K  67584
#define OF_S  101376
#define OF_AH 118784
#define OF_AL 128000
#define OF_V  137216
#define SM_ATTN_BYTES (OF_V + 2 * 9216)   // 155648

__global__ __launch_bounds__(256) void k_attn()
{
    extern __shared__ __align__(128) char smc[];
    const uint32_t S0 = smem_to_u32(smc);
    float* smf = (float*)smc;
    const int l = blockIdx.x;
    const int tid = threadIdx.x;
    const int wid = tid >> 5, lane = tid & 31;
    const int rq = lane >> 2, p4 = (lane & 3) << 2;
    const int m0 = (wid & 3) * 16;
    const int n0 = (wid >> 2) * 32;

    // ---- load Q(x hi/lo) and K(z single) ----
    for (int idx = tid; idx < 2048; idx += 256) {
        int row = idx >> 5, ch = idx & 31;
        size_t g = ((size_t)row * NL + l) * NC + ch * 8;
        uint32_t so = (uint32_t)(row * 528 + ch * 16);
        cpa16(S0 + OF_QH + so, g_xh + g);
        cpa16(S0 + OF_QL + so, g_xl + g);
        cpa16(S0 + OF_K  + so, g_zf + g);
    }
    for (int idx = tid; idx < 512; idx += 256) {
        int d = idx >> 3, ch = idx & 7;
        size_t g = ((size_t)d * NL + l) * NC + ch * 8;
        cpa16(S0 + OF_V + (uint32_t)(d * 144 + ch * 16), g_vf + g);
    }
    asm volatile("cp.async.commit_group;" ::: "memory");
    asm volatile("cp.async.wait_group 0;" ::: "memory");
    __syncthreads();

    // ---- scores S[b][d] = (x_b . z_d)/16 ; 2-term one-sided split ----
    float acc[4][4];
#pragma unroll
    for (int i = 0; i < 4; i++)
#pragma unroll
        for (int j = 0; j < 4; j++) acc[i][j] = 0.f;

#pragma unroll
    for (int kk = 0; kk < 16; kk++) {
        uint32_t abase = S0 + (uint32_t)((m0 + rq) * 528 + kk * 32 + p4);
        uint32_t ah[4], al[4];
        ah[0] = lds32v(abase + OF_QH);
        ah[1] = lds32v(abase + OF_QH + 8 * 528);
        ah[2] = lds32v(abase + OF_QH + 16);
        ah[3] = lds32v(abase + OF_QH + 8 * 528 + 16);
        al[0] = lds32v(abase + OF_QL);
        al[1] = lds32v(abase + OF_QL + 8 * 528);
        al[2] = lds32v(abase + OF_QL + 16);
        al[3] = lds32v(abase + OF_QL + 8 * 528 + 16);
#pragma unroll
        for (int nt = 0; nt < 4; nt++) {
            uint32_t bbase = S0 + OF_K + (uint32_t)((n0 + nt * 8 + rq) * 528 + kk * 32 + p4);
            uint32_t bf[2];
            bf[0] = lds32v(bbase);
            bf[1] = lds32v(bbase + 16);
            MMAF16(acc[nt], ah, bf);
            MMAF16(acc[nt], al, bf);
        }
    }
#pragma unroll
    for (int nt = 0; nt < 4; nt++) {
        int r = m0 + rq;
        int c = n0 + nt * 8 + (lane & 3) * 2;
        *(float2*)&smf[(OF_S >> 2) + r * 68 + c]       = make_float2(acc[nt][0] * 0.0625f, acc[nt][1] * 0.0625f);
        *(float2*)&smf[(OF_S >> 2) + (r + 8) * 68 + c] = make_float2(acc[nt][2] * 0.0625f, acc[nt][3] * 0.0625f);
    }
    __syncthreads();

    // ---- softmax over d, write att as fp16 hi/lo ----
    if (tid < 64) {
        float* row = &smf[(OF_S >> 2) + tid * 68];
        float m = row[0];
        for (int d = 1; d < 64; d++) m = fmaxf(m, row[d]);
        float s = 0.f;
        float e[64];
        for (int d = 0; d < 64; d++) { e[d] = __expf(row[d] - m); s += e[d]; }
        float inv = 1.f / s;
        for (int d = 0; d < 64; d += 2) {
            float w0 = e[d] * inv, w1 = e[d + 1] * inv;
            __half h0 = __float2half(w0);
            __half h1 = __float2half(w1);
            __half2 hh; hh.x = h0; hh.y = h1;
            *(__half2*)(smc + OF_AH + tid * 144 + d * 2) = hh;
            __half2 ll;
            ll.x = __float2half(w0 - __half2float(h0));
            ll.y = __float2half(w1 - __half2float(h1));
            *(__half2*)(smc + OF_AL + tid * 144 + d * 2) = ll;
        }
        smf[(OF_S >> 2) + tid] = 0.f;        // GN sum
        smf[(OF_S >> 2) + 64 + tid] = 0.f;   // GN sumsq
    }

    // ---- AV: virt[b][c] = sum_d att[b][d] v[d][c], chunked over c ----
    float gs0 = 0.f, gss0 = 0.f, gs1 = 0.f, gss1 = 0.f;

    for (int cc = 0; cc < 4; cc++) {
        __syncthreads();
        if (cc < 3) {
            int nb = (cc + 1) & 1;
            for (int idx = tid; idx < 512; idx += 256) {
                int d = idx >> 3, ch = idx & 7;
                size_t g = ((size_t)d * NL + l) * NC + (cc + 1) * 64 + ch * 8;
                cpa16(S0 + OF_V + (uint32_t)(nb * 9216 + d * 144 + ch * 16), g_vf + g);
            }
            asm volatile("cp.async.commit_group;" ::: "memory");
            asm volatile("cp.async.wait_group 1;" ::: "memory");
        } else {
            asm volatile("cp.async.wait_group 0;" ::: "memory");
        }
        __syncthreads();

        const uint32_t VB = S0 + OF_V + (uint32_t)((cc & 1) * 9216);

        float av[4][4];
#pragma unroll
        for (int i = 0; i < 4; i++)
#pragma unroll
            for (int j = 0; j < 4; j++) av[i][j] = 0.f;

#pragma unroll
        for (int k = 0; k < 4; k++) {
            uint32_t abase = S0 + (uint32_t)((m0 + rq) * 144 + k * 32 + p4);
            uint32_t ah[4], al[4];
            ah[0] = lds32v(abase + OF_AH);
            ah[1] = lds32v(abase + OF_AH + 8 * 144);
            ah[2] = lds32v(abase + OF_AH + 16);
            ah[3] = lds32v(abase + OF_AH + 8 * 144 + 16);
            al[0] = lds32v(abase + OF_AL);
            al[1] = lds32v(abase + OF_AL + 8 * 144);
            al[2] = lds32v(abase + OF_AL + 16);
            al[3] = lds32v(abase + OF_AL + 8 * 144 + 16);
            int d0 = k * 16 + (lane & 3) * 2;
#pragma unroll
            for (int nt = 0; nt < 4; nt++) {
                int c = n0 + nt * 8 + rq;
                uint32_t a0 = VB + (uint32_t)(d0 * 144 + c * 2);
                uint32_t bf[2];
                bf[0] = lds_u16pair(a0, a0 + 144);
                bf[1] = lds_u16pair(a0 + 8 * 144, a0 + 9 * 144);
                MMAF16(av[nt], ah, bf);
                MMAF16(av[nt], al, bf);
            }
        }
#pragma unroll
        for (int nt = 0; nt < 4; nt++) {
            int b0r = m0 + rq;
            int c = cc * 64 + n0 + nt * 8 + (lane & 3) * 2;
            float v0 = av[nt][0], v1 = av[nt][1], v2 = av[nt][2], v3 = av[nt][3];
            __half2 h01; h01.x = __float2half(v0); h01.y = __float2half(v1);
            __half2 h23; h23.x = __float2half(v2); h23.y = __float2half(v3);
            *(__half2*)(g_vtf + ((size_t)b0r * NL + l) * NC + c)       = h01;
            *(__half2*)(g_vtf + ((size_t)(b0r + 8) * NL + l) * NC + c) = h23;
            gs0  += v0 + v1;
            gss0 += v0 * v0 + v1 * v1;
            gs1  += v2 + v3;
            gss1 += v2 * v2 + v3 * v3;
        }
    }

    gs0  += __shfl_xor_sync(0xffffffffu, gs0, 1);  gs0  += __shfl_xor_sync(0xffffffffu, gs0, 2);
    gss0 += __shfl_xor_sync(0xffffffffu, gss0, 1); gss0 += __shfl_xor_sync(0xffffffffu, gss0, 2);
    gs1  += __shfl_xor_sync(0xffffffffu, gs1, 1);  gs1  += __shfl_xor_sync(0xffffffffu, gs1, 2);
    gss1 += __shfl_xor_sync(0xffffffffu, gss1, 1); gss1 += __shfl_xor_sync(0xffffffffu, gss1, 2);
    if ((lane & 3) == 0) {
        atomicAdd(&smf[(OF_S >> 2) + m0 + rq], gs0);
        atomicAdd(&smf[(OF_S >> 2) + 64 + m0 + rq], gss0);
        atomicAdd(&smf[(OF_S >> 2) + m0 + rq + 8], gs1);
        atomicAdd(&smf[(OF_S >> 2) + 64 + m0 + rq + 8], gss1);
    }
    __syncthreads();
    if (tid < 64) {
        atomicAdd(&g_psum[tid],   smf[(OF_S >> 2) + tid]);
        atomicAdd(&g_psumsq[tid], smf[(OF_S >> 2) + 64 + tid]);
    }
}

// ================= K: stats =================
__global__ void k_stats()
{
    int b = threadIdx.x;
    if (b < NB) {
        const float n = (float)NC * (float)NL;
        float mean = g_psum[b] / n;
        float var  = g_psumsq[b] / n - mean * mean;
        if (var < 0.f) var = 0.f;
        g_mean[b] = mean;
        g_rstd[b] = rsqrtf(var + 1e-5f);
    }
}

// ================= K: GN+ReLU on virt(fp16) -> single fp16 =================
__global__ __launch_bounds__(256) void k_prep2(const float* __restrict__ gamma, const float* __restrict__ beta)
{
    size_t i4 = ((size_t)blockIdx.x * 256 + threadIdx.x) * 4;
    int c = (int)(i4 & 255);
    int b = (int)(i4 >> 20);
    float mean = g_mean[b], rstd = g_rstd[b];
    __half2 v01 = *(const __half2*)(g_vtf + i4);
    __half2 v23 = *(const __half2*)(g_vtf + i4 + 2);
    float vv[4] = { __half2float(v01.x), __half2float(v01.y),
                    __half2float(v23.x), __half2float(v23.y) };
    __half2 h0, h1;
    h0.x = __float2half(fmaxf(fmaf((vv[0] - mean) * rstd, gamma[c + 0], beta[c + 0]), 0.f));
    h0.y = __float2half(fmaxf(fmaf((vv[1] - mean) * rstd, gamma[c + 1], beta[c + 1]), 0.f));
    h1.x = __float2half(fmaxf(fmaf((vv[2] - mean) * rstd, gamma[c + 2], beta[c + 2]), 0.f));
    h1.y = __float2half(fmaxf(fmaf((vv[3] - mean) * rstd, gamma[c + 3], beta[c + 3]), 0.f));
    *(__half2*)(g_nh + i4)     = h0;
    *(__half2*)(g_nh + i4 + 2) = h1;
}

// ================= launch =================
extern "C" void kernel_launch(void* const* d_in, const int* in_sizes, int n_in,
                              void* d_out, int out_size)
{
    const float* x     = (const float*)d_in[0];
    const float* Wq    = (const float*)d_in[1];
    const float* Wk    = (const float*)d_in[2];
    const float* Wv    = (const float*)d_in[3];
    const float* Wc    = (const float*)d_in[4];
    const float* Wout  = (const float*)d_in[5];
    const float* gamma = (const float*)d_in[6];
    const float* beta  = (const float*)d_in[7];
    float* out = (float*)d_out;

    cudaFuncSetAttribute(k_attn,    cudaFuncAttributeMaxDynamicSharedMemorySize, SM_ATTN_BYTES);
    cudaFuncSetAttribute(k_gemm<0>, cudaFuncAttributeMaxDynamicSharedMemorySize, SMEM_GEMM0);
    cudaFuncSetAttribute(k_gemm<1>, cudaFuncAttributeMaxDynamicSharedMemorySize, SMEM_GEMM1);

    k_wprep<<<161, 256>>>(Wq, Wk, Wout, Wc, Wv);
    k_prep0<<<dim3(64, 4, 64), 256>>>(x);
    k_gemm<0><<<dim3(2048, 4), 256, SMEM_GEMM0>>>(nullptr);   // z (split), v (single)
    k_attn<<<NL, 256, SM_ATTN_BYTES>>>();
    k_stats<<<1, 64>>>();
    k_prep2<<<65536, 256>>>(gamma, beta);
    k_gemm<1><<<dim3(2048, 2), 256, SMEM_GEMM1>>>(out);       // out = Wout x + Wz gn (single-A)
}

// round 15
// speedup vs baseline: 1.8706x; 1.0016x over previous
#include <cuda_runtime.h>
#include <cuda_fp16.h>
#include <cstdint>

#define NB   64
#define NC   256
#define NL   4096
#define NOUT 256
#define NTOK (NB * NL)   // 262144 tokens

// ================= helpers =================
__device__ __forceinline__ uint32_t smem_to_u32(const void* p) {
    uint32_t a;
    asm("{ .reg .u64 t; cvta.to.shared.u64 t, %1; cvt.u32.u64 %0, t; }" : "=r"(a) : "l"(p));
    return a;
}
__device__ __forceinline__ void cpa16(uint32_t s, const void* g) {
    asm volatile("cp.async.cg.shared.global [%0], [%1], 16;" :: "r"(s), "l"(g) : "memory");
}
__device__ __forceinline__ uint32_t lds32v(uint32_t a) {
    uint32_t v;
    asm volatile("ld.shared.b32 %0, [%1];" : "=r"(v) : "r"(a) : "memory");
    return v;
}
__device__ __forceinline__ uint32_t lds_u16pair(uint32_t a0, uint32_t a1) {
    uint32_t lo, hi;
    asm volatile("ld.shared.u16 %0, [%1];" : "=r"(lo) : "r"(a0) : "memory");
    asm volatile("ld.shared.u16 %0, [%1];" : "=r"(hi) : "r"(a1) : "memory");
    return lo | (hi << 16);
}
#define MMAF16(d, a, b) \
    asm volatile("mma.sync.aligned.m16n8k16.row.col.f32.f16.f16.f32 " \
        "{%0,%1,%2,%3},{%4,%5,%6,%7},{%8,%9},{%0,%1,%2,%3};" \
        : "+f"((d)[0]), "+f"((d)[1]), "+f"((d)[2]), "+f"((d)[3]) \
        : "r"((a)[0]), "r"((a)[1]), "r"((a)[2]), "r"((a)[3]), "r"((b)[0]), "r"((b)[1]))

// ================= scratch (device globals; referenced ONLY in device code) =================
__device__ __align__(256) __half g_xh  [(long long)NTOK * NC];
__device__ __align__(256) __half g_xl  [(long long)NTOK * NC];
__device__ __align__(256) __half g_zf  [(long long)NTOK * NC];
__device__ __align__(256) __half g_vf  [(long long)NTOK * NC];
__device__ __align__(256) __half g_vtf [(long long)NTOK * NC];   // virt (fp16)
__device__ __align__(256) __half g_Gf [NC * NC];
__device__ __align__(256) __half g_wvf[NC * NC];
__device__ __align__(256) __half g_wof[NC * NC];
__device__ __align__(256) __half g_wzf[NC * NC];
__device__ float g_psum[NB], g_psumsq[NB], g_mean[NB], g_rstd[NB];

// ================= K: fused weight prep =================
__global__ __launch_bounds__(256) void k_wprep(
    const float* __restrict__ Wq, const float* __restrict__ Wk,
    const float* __restrict__ Wo, const float* __restrict__ Wc,
    const float* __restrict__ Wv)
{
    const int bx = blockIdx.x;
    const int tid = threadIdx.x;

    if (bx >= 160) {
        if (tid < NB) { g_psum[tid] = 0.f; g_psumsq[tid] = 0.f; }
        return;
    }
    if (bx >= 32) {
        int gid = (bx - 32) * 256 + tid;
        int arr = gid >> 14;
        int off = (gid & 16383) * 4;
        const float* src = (arr == 0) ? Wv : Wo;
        __half* dst = (arr == 0) ? g_wvf : g_wof;
        float4 v = *(const float4*)(src + off);
        __half2 h0; h0.x = __float2half(v.x); h0.y = __float2half(v.y);
        __half2 h1; h1.x = __float2half(v.z); h1.y = __float2half(v.w);
        *(__half2*)(dst + off)     = h0;
        *(__half2*)(dst + off + 2) = h1;
        return;
    }

    __shared__ float sA[16][68], sB[16][68];
    const bool isG = (bx < 16);
    const int bb = isG ? bx : bx - 16;
    const int e0 = (bb & 3) << 6;
    const int f0 = (bb >> 2) << 6;
    const int tx = tid & 15, ty = tid >> 4;

    float acc[4][4];
#pragma unroll
    for (int i = 0; i < 4; i++)
#pragma unroll
        for (int j = 0; j < 4; j++) acc[i][j] = 0.f;

    for (int k0 = 0; k0 < NC; k0 += 16) {
#pragma unroll
        for (int i = 0; i < 4; i++) {
            int r = (tid >> 6) + i * 4, col = tid & 63;
            if (isG) {
                sA[r][col] = Wq[(size_t)(k0 + r) * NC + e0 + col];
                sB[r][col] = Wk[(size_t)(k0 + r) * NC + f0 + col];
            } else {
                sA[r][col] = Wo[(size_t)(e0 + col) * NC + k0 + r];
                sB[r][col] = Wc[(size_t)(k0 + r) * NC + f0 + col];
            }
        }
        __syncthreads();
#pragma unroll
        for (int kk = 0; kk < 16; kk++) {
            float a[4], b2[4];
#pragma unroll
            for (int i = 0; i < 4; i++) { a[i] = sA[kk][ty * 4 + i]; b2[i] = sB[kk][tx * 4 + i]; }
#pragma unroll
            for (int i = 0; i < 4; i++)
#pragma unroll
                for (int j = 0; j < 4; j++) acc[i][j] = fmaf(a[i], b2[j], acc[i][j]);
        }
        __syncthreads();
    }
    __half* dst = isG ? g_Gf : g_wzf;
#pragma unroll
    for (int i = 0; i < 4; i++)
#pragma unroll
        for (int j = 0; j < 4; j++)
            dst[(e0 + ty * 4 + i) * NC + f0 + tx * 4 + j] = __float2half(acc[i][j]);
}

// ================= K: transpose x -> fp16 hi/lo split (token-major) =================
__global__ __launch_bounds__(256) void k_prep0(const float* __restrict__ x)
{
    __shared__ float tile[64][65];
    const int b  = blockIdx.z;
    const int l0 = blockIdx.x << 6;
    const int c0 = blockIdx.y << 6;
    const int tid = threadIdx.x;
    const int tx = tid & 63, ty = tid >> 6;

    const float* xp = x + (size_t)b * NC * NL + (size_t)c0 * NL + l0;
#pragma unroll
    for (int i = 0; i < 16; i++) {
        int r = i * 4 + ty;
        tile[r][tx] = xp[(size_t)r * NL + tx];
    }
    __syncthreads();
#pragma unroll
    for (int i = 0; i < 16; i++) {
        int lr = i * 4 + ty;
        float v = tile[tx][lr];
        size_t idx = ((size_t)(b * NL + l0 + lr)) * NC + c0 + tx;
        __half h = __float2half(v);
        g_xh[idx] = h;
        g_xl[idx] = __float2half(v - __half2float(h));
    }
}

// ================= K: fp16 GEMM, 4-stage pipeline =================
// KIND 0: grid (2048, 4): y<2 -> z = G x (A split hi/lo); y>=2 -> v = Wv x (single)
// KIND 1: grid (2048, 2): out = Wout x + Wz gn; gn = GN+ReLU applied at fragment
//         load from raw fp16 virt (scale/bias per channel precomputed per CTA).
#define WROWB   48
#define A0ROWB  80
#define A1ROWB  48
#define STB0    (128 * A0ROWB + 128 * WROWB)   // 16384
#define STB1    (128 * A1ROWB + 128 * WROWB)   // 12288
#define NPIPE   4
#define SMEM_GEMM0 (NPIPE * STB0)              // 65536
#define SMEM_GEMM1 (NPIPE * STB1 + 2048)       // 51200 (+sc/bc)

template<int KIND>
__global__ __launch_bounds__(256) void k_gemm(
    float* __restrict__ outf,
    const float* __restrict__ gamma, const float* __restrict__ beta)
{
    extern __shared__ __align__(128) char smem[];
    const uint32_t sbase = smem_to_u32(smem);
    const int tid  = threadIdx.x;
    const int wid  = tid >> 5;
    const int lane = tid & 31;
    const int t0   = blockIdx.x << 7;
    const int NS   = (KIND == 0) ? 16 : 32;
    constexpr int AR  = (KIND == 0) ? A0ROWB : A1ROWB;
    constexpr int STB = (KIND == 0) ? STB0 : STB1;
    constexpr uint32_t HALF = 128u * (uint32_t)AR;

    float* scp = (float*)(smem + NPIPE * STB1);       // KIND1 only
    float* bcp = scp + 256;
    if (KIND == 1) {
        int b = t0 >> 12;
        float mu = g_mean[b], rho = g_rstd[b];
        int c = tid;
        float ga = gamma[c], be = beta[c];
        scp[c] = rho * ga;
        bcp[c] = be - mu * rho * ga;
    }

    int o0, wsel = 0;
    if (KIND == 0) { wsel = blockIdx.y >> 1; o0 = (blockIdx.y & 1) << 7; }
    else           { o0 = blockIdx.y << 7; }

    const int wm = wid & 1;
    const int wn = wid >> 1;

    auto load_stage = [&](int s) {
        const __half *Ah, *Al, *Wf;
        int k0;
        if (KIND == 0) {
            Ah = g_xh; Al = g_xl;
            Wf = wsel ? g_wvf : g_Gf;
            k0 = s << 4;
        } else {
            Al = nullptr;
            if (s < 16) { Ah = g_xh;  Wf = g_wof; k0 = s << 4; }
            else        { Ah = g_vtf; Wf = g_wzf; k0 = (s - 16) << 4; }
        }
        const uint32_t buf = sbase + (uint32_t)(s & (NPIPE - 1)) * (uint32_t)STB;
        if (KIND == 0) {
#pragma unroll
            for (int i = 0; i < 3; i++) {
                int idx = tid + (i << 8);
                if (idx < 512) {
                    int r = idx >> 2, ch = idx & 3;
                    if (!(wsel && ch >= 2)) {
                        const __half* src = ((ch < 2) ? Ah : Al) + (size_t)(t0 + r) * NC + k0 + ((ch & 1) << 3);
                        cpa16(buf + (uint32_t)(r * AR + (ch << 4)), src);
                    }
                } else {
                    int j = idx - 512;
                    int r = j >> 1, ch = j & 1;
                    const __half* src = Wf + (size_t)(o0 + r) * NC + k0 + (ch << 3);
                    cpa16(buf + HALF + (uint32_t)(r * WROWB + (ch << 4)), src);
                }
            }
        } else {
#pragma unroll
            for (int i = 0; i < 2; i++) {
                int idx = tid + (i << 8);
                if (idx < 256) {
                    int r = idx >> 1, ch = idx & 1;
                    const __half* src = Ah + (size_t)(t0 + r) * NC + k0 + (ch << 3);
                    cpa16(buf + (uint32_t)(r * AR + (ch << 4)), src);
                } else {
                    int j = idx - 256;
                    int r = j >> 1, ch = j & 1;
                    const __half* src = Wf + (size_t)(o0 + r) * NC + k0 + (ch << 3);
                    cpa16(buf + HALF + (uint32_t)(r * WROWB + (ch << 4)), src);
                }
            }
        }
        asm volatile("cp.async.commit_group;" ::: "memory");
    };

    float acc[4][4][4];
#pragma unroll
    for (int a = 0; a < 4; a++)
#pragma unroll
        for (int b = 0; b < 4; b++)
#pragma unroll
            for (int c = 0; c < 4; c++) acc[a][b][c] = 0.f;

    const int rq = lane >> 2;
    const int p4 = (lane & 3) << 2;

    load_stage(0);
    load_stage(1);
    load_stage(2);

    for (int s = 0; s < NS; s++) {
        int rem = NS - 1 - s;
        if (rem >= 2)      asm volatile("cp.async.wait_group 2;" ::: "memory");
        else if (rem == 1) asm volatile("cp.async.wait_group 1;" ::: "memory");
        else               asm volatile("cp.async.wait_group 0;" ::: "memory");
        __syncthreads();
        if (s + 3 < NS) load_stage(s + 3);

        const uint32_t bufA = sbase + (uint32_t)(s & (NPIPE - 1)) * (uint32_t)STB;
        const uint32_t bufW = bufA + HALF;

        uint32_t ah[4][4], al[4][4], bf[4][2];
#pragma unroll
        for (int mt = 0; mt < 4; mt++) {
            uint32_t base = bufA + (uint32_t)((wm * 64 + mt * 16 + rq) * AR + p4);
            ah[mt][0] = lds32v(base);
            ah[mt][1] = lds32v(base + 8 * AR);
            ah[mt][2] = lds32v(base + 16);
            ah[mt][3] = lds32v(base + 8 * AR + 16);
            if (KIND == 0 && !wsel) {
                al[mt][0] = lds32v(base + 32);
                al[mt][1] = lds32v(base + 8 * AR + 32);
                al[mt][2] = lds32v(base + 48);
                al[mt][3] = lds32v(base + 8 * AR + 48);
            }
        }
        if (KIND == 1 && s >= 16) {
            // GN+ReLU transform on raw virt fragments
            int cb = ((s - 16) << 4) + ((lane & 3) << 1);
#pragma unroll
            for (int j = 0; j < 4; j++) {
                int c = cb + ((j >> 1) & 1) * 8;
                float s0 = scp[c], s1 = scp[c + 1];
                float b0 = bcp[c], b1 = bcp[c + 1];
#pragma unroll
                for (int mt = 0; mt < 4; mt++) {
                    __half2 h = *(__half2*)&ah[mt][j];
                    float v0 = fmaxf(fmaf(__half2float(h.x), s0, b0), 0.f);
                    float v1 = fmaxf(fmaf(__half2float(h.y), s1, b1), 0.f);
                    __half2 r = __floats2half2_rn(v0, v1);
                    ah[mt][j] = *(uint32_t*)&r;
                }
            }
        }
#pragma unroll
        for (int nt = 0; nt < 4; nt++) {
            uint32_t base = bufW + (uint32_t)((wn * 32 + nt * 8 + rq) * WROWB + p4);
            bf[nt][0] = lds32v(base);
            bf[nt][1] = lds32v(base + 16);
        }
#pragma unroll
        for (int mt = 0; mt < 4; mt++)
#pragma unroll
            for (int nt = 0; nt < 4; nt++) {
                MMAF16(acc[mt][nt], ah[mt], bf[nt]);
                if (KIND == 0 && !wsel) MMAF16(acc[mt][nt], al[mt], bf[nt]);
            }
    }

    // epilogue
    const int fr = lane >> 2;
    const int fc = (lane & 3) * 2;
#pragma unroll
    for (int mt = 0; mt < 4; mt++) {
#pragma unroll
        for (int nt = 0; nt < 4; nt++) {
            int r = wm * 64 + mt * 16 + fr;
            int c = wn * 32 + nt * 8 + fc;
            float d0 = acc[mt][nt][0], d1 = acc[mt][nt][1];
            float d2 = acc[mt][nt][2], d3 = acc[mt][nt][3];
            if (KIND == 0) {
                __half* dst = wsel ? g_vf : g_zf;
                __half2 h01; h01.x = __float2half(d0); h01.y = __float2half(d1);
                __half2 h23; h23.x = __float2half(d2); h23.y = __float2half(d3);
                *(__half2*)(dst + (size_t)(t0 + r) * NC + o0 + c)     = h01;
                *(__half2*)(dst + (size_t)(t0 + r + 8) * NC + o0 + c) = h23;
            } else {
                const int b = t0 >> 12;
                int l = (t0 & 4095) + r;
                outf[((size_t)(b * NOUT + o0 + c))     * NL + l] = d0;
                outf[((size_t)(b * NOUT + o0 + c + 1)) * NL + l] = d1;
                outf[((size_t)(b * NOUT + o0 + c))     * NL + l + 8] = d2;
                outf[((size_t)(b * NOUT + o0 + c + 1)) * NL + l + 8] = d3;
            }
        }
    }
}

// ================= K: tensorized per-l batch attention (512 threads) + GN partials =================
// smem: QH 0 (64x528), QL 33792, K 67584, S 101376 (fp32 [64][68], reused as GN accum),
//       AH 118784 (64x144, single fp16 att), V 128000 (2 x 64x144)
#define OF_QH 0
#define OF_QL 33792
#define OF_K  67584
#define OF_S  101376
#define OF_AH 118784
#define OF_V  128000
#define SM_ATTN_BYTES (OF_V + 2 * 9216)   // 146432

__global__ __launch_bounds__(512) void k_attn()
{
    extern __shared__ __align__(128) char smc[];
    const uint32_t S0 = smem_to_u32(smc);
    float* smf = (float*)smc;
    const int l = blockIdx.x;
    const int tid = threadIdx.x;
    const int wid = tid >> 5, lane = tid & 31;
    const int rq = lane >> 2, p4 = (lane & 3) << 2;
    const int m0 = (wid & 3) * 16;        // 4 m-warps
    const int n0 = (wid >> 2) * 16;       // 4 n-warps

    // ---- load Q(x hi/lo) and K(z single) ----
    for (int idx = tid; idx < 2048; idx += 512) {
        int row = idx >> 5, ch = idx & 31;
        size_t g = ((size_t)row * NL + l) * NC + ch * 8;
        uint32_t so = (uint32_t)(row * 528 + ch * 16);
        cpa16(S0 + OF_QH + so, g_xh + g);
        cpa16(S0 + OF_QL + so, g_xl + g);
        cpa16(S0 + OF_K  + so, g_zf + g);
    }
    for (int idx = tid; idx < 512; idx += 512) {
        int d = idx >> 3, ch = idx & 7;
        size_t g = ((size_t)d * NL + l) * NC + ch * 8;
        cpa16(S0 + OF_V + (uint32_t)(d * 144 + ch * 16), g_vf + g);
    }
    asm volatile("cp.async.commit_group;" ::: "memory");
    asm volatile("cp.async.wait_group 0;" ::: "memory");
    __syncthreads();

    // ---- scores S[b][d] = (x_b . z_d)/16 ; 2-term one-sided split ----
    float acc[2][4];
#pragma unroll
    for (int i = 0; i < 2; i++)
#pragma unroll
        for (int j = 0; j < 4; j++) acc[i][j] = 0.f;

#pragma unroll
    for (int kk = 0; kk < 16; kk++) {
        uint32_t abase = S0 + (uint32_t)((m0 + rq) * 528 + kk * 32 + p4);
        uint32_t ah[4], al[4];
        ah[0] = lds32v(abase + OF_QH);
        ah[1] = lds32v(abase + OF_QH + 8 * 528);
        ah[2] = lds32v(abase + OF_QH + 16);
        ah[3] = lds32v(abase + OF_QH + 8 * 528 + 16);
        al[0] = lds32v(abase + OF_QL);
        al[1] = lds32v(abase + OF_QL + 8 * 528);
        al[2] = lds32v(abase + OF_QL + 16);
        al[3] = lds32v(abase + OF_QL + 8 * 528 + 16);
#pragma unroll
        for (int nt = 0; nt < 2; nt++) {
            uint32_t bbase = S0 + OF_K + (uint32_t)((n0 + nt * 8 + rq) * 528 + kk * 32 + p4);
            uint32_t bf[2];
            bf[0] = lds32v(bbase);
            bf[1] = lds32v(bbase + 16);
            MMAF16(acc[nt], ah, bf);
            MMAF16(acc[nt], al, bf);
        }
    }
#pragma unroll
    for (int nt = 0; nt < 2; nt++) {
        int r = m0 + rq;
        int c = n0 + nt * 8 + (lane & 3) * 2;
        *(float2*)&smf[(OF_S >> 2) + r * 68 + c]       = make_float2(acc[nt][0] * 0.0625f, acc[nt][1] * 0.0625f);
        *(float2*)&smf[(OF_S >> 2) + (r + 8) * 68 + c] = make_float2(acc[nt][2] * 0.0625f, acc[nt][3] * 0.0625f);
    }
    __syncthreads();

    // ---- softmax over d, write att as single fp16 ----
    if (tid < 64) {
        float* row = &smf[(OF_S >> 2) + tid * 68];
        float m = row[0];
        for (int d = 1; d < 64; d++) m = fmaxf(m, row[d]);
        float s = 0.f;
        float e[64];
        for (int d = 0; d < 64; d++) { e[d] = __expf(row[d] - m); s += e[d]; }
        float inv = 1.f / s;
        for (int d = 0; d < 64; d += 2) {
            __half2 hh = __floats2half2_rn(e[d] * inv, e[d + 1] * inv);
            *(__half2*)(smc + OF_AH + tid * 144 + d * 2) = hh;
        }
        smf[(OF_S >> 2) + tid] = 0.f;        // GN sum
        smf[(OF_S >> 2) + 64 + tid] = 0.f;   // GN sumsq
    }

    // ---- AV: virt[b][c] = sum_d att[b][d] v[d][c], chunked over c ----
    float gs0 = 0.f, gss0 = 0.f, gs1 = 0.f, gss1 = 0.f;

    for (int cc = 0; cc < 4; cc++) {
        __syncthreads();
        if (cc < 3) {
            int nb = (cc + 1) & 1;
            for (int idx = tid; idx < 512; idx += 512) {
                int d = idx >> 3, ch = idx & 7;
                size_t g = ((size_t)d * NL + l) * NC + (cc + 1) * 64 + ch * 8;
                cpa16(S0 + OF_V + (uint32_t)(nb * 9216 + d * 144 + ch * 16), g_vf + g);
            }
            asm volatile("cp.async.commit_group;" ::: "memory");
            asm volatile("cp.async.wait_group 1;" ::: "memory");
        } else {
            asm volatile("cp.async.wait_group 0;" ::: "memory");
        }
        __syncthreads();

        const uint32_t VB = S0 + OF_V + (uint32_t)((cc & 1) * 9216);

        float av[2][4];
#pragma unroll
        for (int i = 0; i < 2; i++)
#pragma unroll
            for (int j = 0; j < 4; j++) av[i][j] = 0.f;

#pragma unroll
        for (int k = 0; k < 4; k++) {
            uint32_t abase = S0 + OF_AH + (uint32_t)((m0 + rq) * 144 + k * 32 + p4);
            uint32_t ah[4];
            ah[0] = lds32v(abase);
            ah[1] = lds32v(abase + 8 * 144);
            ah[2] = lds32v(abase + 16);
            ah[3] = lds32v(abase + 8 * 144 + 16);
            int d0 = k * 16 + (lane & 3) * 2;
#pragma unroll
            for (int nt = 0; nt < 2; nt++) {
                int c = n0 + nt * 8 + rq;
                uint32_t a0 = VB + (uint32_t)(d0 * 144 + c * 2);
                uint32_t bf[2];
                bf[0] = lds_u16pair(a0, a0 + 144);
                bf[1] = lds_u16pair(a0 + 8 * 144, a0 + 9 * 144);
                MMAF16(av[nt], ah, bf);
            }
        }
#pragma unroll
        for (int nt = 0; nt < 2; nt++) {
            int b0r = m0 + rq;
            int c = cc * 64 + n0 + nt * 8 + (lane & 3) * 2;
            float v0 = av[nt][0], v1 = av[nt][1], v2 = av[nt][2], v3 = av[nt][3];
            __half2 h01 = __floats2half2_rn(v0, v1);
            __half2 h23 = __floats2half2_rn(v2, v3);
            *(__half2*)(g_vtf + ((size_t)b0r * NL + l) * NC + c)       = h01;
            *(__half2*)(g_vtf + ((size_t)(b0r + 8) * NL + l) * NC + c) = h23;
            gs0  += v0 + v1;
            gss0 += v0 * v0 + v1 * v1;
            gs1  += v2 + v3;
            gss1 += v2 * v2 + v3 * v3;
        }
    }

    gs0  += __shfl_xor_sync(0xffffffffu, gs0, 1);  gs0  += __shfl_xor_sync(0xffffffffu, gs0, 2);
    gss0 += __shfl_xor_sync(0xffffffffu, gss0, 1); gss0 += __shfl_xor_sync(0xffffffffu, gss0, 2);
    gs1  += __shfl_xor_sync(0xffffffffu, gs1, 1);  gs1  += __shfl_xor_sync(0xffffffffu, gs1, 2);
    gss1 += __shfl_xor_sync(0xffffffffu, gss1, 1); gss1 += __shfl_xor_sync(0xffffffffu, gss1, 2);
    if ((lane & 3) == 0) {
        atomicAdd(&smf[(OF_S >> 2) + m0 + rq], gs0);
        atomicAdd(&smf[(OF_S >> 2) + 64 + m0 + rq], gss0);
        atomicAdd(&smf[(OF_S >> 2) + m0 + rq + 8], gs1);
        atomicAdd(&smf[(OF_S >> 2) + 64 + m0 + rq + 8], gss1);
    }
    __syncthreads();
    if (tid < 64) {
        atomicAdd(&g_psum[tid],   smf[(OF_S >> 2) + tid]);
        atomicAdd(&g_psumsq[tid], smf[(OF_S >> 2) + 64 + tid]);
    }
}

// ================= K: stats =================
__global__ void k_stats()
{
    int b = threadIdx.x;
    if (b < NB) {
        const float n = (float)NC * (float)NL;
        float mean = g_psum[b] / n;
        float var  = g_psumsq[b] / n - mean * mean;
        if (var < 0.f) var = 0.f;
        g_mean[b] = mean;
        g_rstd[b] = rsqrtf(var + 1e-5f);
    }
}

// ================= launch =================
extern "C" void kernel_launch(void* const* d_in, const int* in_sizes, int n_in,
                              void* d_out, int out_size)
{
    const float* x     = (const float*)d_in[0];
    const float* Wq    = (const float*)d_in[1];
    const float* Wk    = (const float*)d_in[2];
    const float* Wv    = (const float*)d_in[3];
    const float* Wc    = (const float*)d_in[4];
    const float* Wout  = (const float*)d_in[5];
    const float* gamma = (const float*)d_in[6];
    const float* beta  = (const float*)d_in[7];
    float* out = (float*)d_out;

    cudaFuncSetAttribute(k_attn,    cudaFuncAttributeMaxDynamicSharedMemorySize, SM_ATTN_BYTES);
    cudaFuncSetAttribute(k_gemm<0>, cudaFuncAttributeMaxDynamicSharedMemorySize, SMEM_GEMM0);
    cudaFuncSetAttribute(k_gemm<1>, cudaFuncAttributeMaxDynamicSharedMemorySize, SMEM_GEMM1);

    k_wprep<<<161, 256>>>(Wq, Wk, Wout, Wc, Wv);
    k_prep0<<<dim3(64, 4, 64), 256>>>(x);
    k_gemm<0><<<dim3(2048, 4), 256, SMEM_GEMM0>>>(nullptr, nullptr, nullptr); // z (split), v (single)
    k_attn<<<NL, 512, SM_ATTN_BYTES>>>();
    k_stats<<<1, 64>>>();
    k_gemm<1><<<dim3(2048, 2), 256, SMEM_GEMM1>>>(out, gamma, beta);          // out = Wout x + Wz gn
}

// round 16
// speedup vs baseline: 1.8888x; 1.0098x over previous
#include <cuda_runtime.h>
#include <cuda_fp16.h>
#include <cstdint>

#define NB   64
#define NC   256
#define NL   4096
#define NOUT 256
#define NTOK (NB * NL)   // 262144 tokens

// ================= helpers =================
__device__ __forceinline__ uint32_t smem_to_u32(const void* p) {
    uint32_t a;
    asm("{ .reg .u64 t; cvta.to.shared.u64 t, %1; cvt.u32.u64 %0, t; }" : "=r"(a) : "l"(p));
    return a;
}
__device__ __forceinline__ void cpa16(uint32_t s, const void* g) {
    asm volatile("cp.async.cg.shared.global [%0], [%1], 16;" :: "r"(s), "l"(g) : "memory");
}
__device__ __forceinline__ uint32_t lds32v(uint32_t a) {
    uint32_t v;
    asm volatile("ld.shared.b32 %0, [%1];" : "=r"(v) : "r"(a) : "memory");
    return v;
}
#define LDSM_X4(r0, r1, r2, r3, addr) \
    asm volatile("ldmatrix.sync.aligned.m8n8.x4.shared.b16 {%0,%1,%2,%3}, [%4];" \
        : "=r"(r0), "=r"(r1), "=r"(r2), "=r"(r3) : "r"(addr))
#define LDSM_X2T(r0, r1, addr) \
    asm volatile("ldmatrix.sync.aligned.m8n8.x2.trans.shared.b16 {%0,%1}, [%2];" \
        : "=r"(r0), "=r"(r1) : "r"(addr))
#define MMAF16(d, a, b) \
    asm volatile("mma.sync.aligned.m16n8k16.row.col.f32.f16.f16.f32 " \
        "{%0,%1,%2,%3},{%4,%5,%6,%7},{%8,%9},{%0,%1,%2,%3};" \
        : "+f"((d)[0]), "+f"((d)[1]), "+f"((d)[2]), "+f"((d)[3]) \
        : "r"((a)[0]), "r"((a)[1]), "r"((a)[2]), "r"((a)[3]), "r"((b)[0]), "r"((b)[1]))

// ================= scratch (device globals; referenced ONLY in device code) =================
__device__ __align__(256) __half g_xh  [(long long)NTOK * NC];
__device__ __align__(256) __half g_xl  [(long long)NTOK * NC];
__device__ __align__(256) __half g_zf  [(long long)NTOK * NC];
__device__ __align__(256) __half g_vf  [(long long)NTOK * NC];
__device__ __align__(256) __half g_vtf [(long long)NTOK * NC];   // virt (fp16)
__device__ __align__(256) __half g_Gf [NC * NC];
__device__ __align__(256) __half g_wvf[NC * NC];
__device__ __align__(256) __half g_wof[NC * NC];
__device__ __align__(256) __half g_wzf[NC * NC];
__device__ float g_psum[NB], g_psumsq[NB], g_mean[NB], g_rstd[NB];

// ================= K: fused weight prep =================
__global__ __launch_bounds__(256) void k_wprep(
    const float* __restrict__ Wq, const float* __restrict__ Wk,
    const float* __restrict__ Wo, const float* __restrict__ Wc,
    const float* __restrict__ Wv)
{
    const int bx = blockIdx.x;
    const int tid = threadIdx.x;

    if (bx >= 160) {
        if (tid < NB) { g_psum[tid] = 0.f; g_psumsq[tid] = 0.f; }
        return;
    }
    if (bx >= 32) {
        int gid = (bx - 32) * 256 + tid;
        int arr = gid >> 14;
        int off = (gid & 16383) * 4;
        const float* src = (arr == 0) ? Wv : Wo;
        __half* dst = (arr == 0) ? g_wvf : g_wof;
        float4 v = *(const float4*)(src + off);
        __half2 h0; h0.x = __float2half(v.x); h0.y = __float2half(v.y);
        __half2 h1; h1.x = __float2half(v.z); h1.y = __float2half(v.w);
        *(__half2*)(dst + off)     = h0;
        *(__half2*)(dst + off + 2) = h1;
        return;
    }

    __shared__ float sA[16][68], sB[16][68];
    const bool isG = (bx < 16);
    const int bb = isG ? bx : bx - 16;
    const int e0 = (bb & 3) << 6;
    const int f0 = (bb >> 2) << 6;
    const int tx = tid & 15, ty = tid >> 4;

    float acc[4][4];
#pragma unroll
    for (int i = 0; i < 4; i++)
#pragma unroll
        for (int j = 0; j < 4; j++) acc[i][j] = 0.f;

    for (int k0 = 0; k0 < NC; k0 += 16) {
#pragma unroll
        for (int i = 0; i < 4; i++) {
            int r = (tid >> 6) + i * 4, col = tid & 63;
            if (isG) {
                sA[r][col] = Wq[(size_t)(k0 + r) * NC + e0 + col];
                sB[r][col] = Wk[(size_t)(k0 + r) * NC + f0 + col];
            } else {
                sA[r][col] = Wo[(size_t)(e0 + col) * NC + k0 + r];
                sB[r][col] = Wc[(size_t)(k0 + r) * NC + f0 + col];
            }
        }
        __syncthreads();
#pragma unroll
        for (int kk = 0; kk < 16; kk++) {
            float a[4], b2[4];
#pragma unroll
            for (int i = 0; i < 4; i++) { a[i] = sA[kk][ty * 4 + i]; b2[i] = sB[kk][tx * 4 + i]; }
#pragma unroll
            for (int i = 0; i < 4; i++)
#pragma unroll
                for (int j = 0; j < 4; j++) acc[i][j] = fmaf(a[i], b2[j], acc[i][j]);
        }
        __syncthreads();
    }
    __half* dst = isG ? g_Gf : g_wzf;
#pragma unroll
    for (int i = 0; i < 4; i++)
#pragma unroll
        for (int j = 0; j < 4; j++)
            dst[(e0 + ty * 4 + i) * NC + f0 + tx * 4 + j] = __float2half(acc[i][j]);
}

// ================= K: transpose x -> fp16 hi/lo split (token-major) =================
__global__ __launch_bounds__(256) void k_prep0(const float* __restrict__ x)
{
    __shared__ float tile[64][65];
    const int b  = blockIdx.z;
    const int l0 = blockIdx.x << 6;
    const int c0 = blockIdx.y << 6;
    const int tid = threadIdx.x;
    const int tx = tid & 63, ty = tid >> 6;

    const float* xp = x + (size_t)b * NC * NL + (size_t)c0 * NL + l0;
#pragma unroll
    for (int i = 0; i < 16; i++) {
        int r = i * 4 + ty;
        tile[r][tx] = xp[(size_t)r * NL + tx];
    }
    __syncthreads();
#pragma unroll
    for (int i = 0; i < 16; i++) {
        int lr = i * 4 + ty;
        float v = tile[tx][lr];
        size_t idx = ((size_t)(b * NL + l0 + lr)) * NC + c0 + tx;
        __half h = __float2half(v);
        g_xh[idx] = h;
        g_xl[idx] = __float2half(v - __half2float(h));
    }
}

// ================= K: fp16 GEMM, 4-stage pipeline =================
#define WROWB   48
#define A0ROWB  80
#define A1ROWB  48
#define STB0    (128 * A0ROWB + 128 * WROWB)   // 16384
#define STB1    (128 * A1ROWB + 128 * WROWB)   // 12288
#define NPIPE   4
#define SMEM_GEMM0 (NPIPE * STB0)              // 65536
#define SMEM_GEMM1 (NPIPE * STB1 + 2048)       // 51200

template<int KIND>
__global__ __launch_bounds__(256) void k_gemm(
    float* __restrict__ outf,
    const float* __restrict__ gamma, const float* __restrict__ beta)
{
    extern __shared__ __align__(128) char smem[];
    const uint32_t sbase = smem_to_u32(smem);
    const int tid  = threadIdx.x;
    const int wid  = tid >> 5;
    const int lane = tid & 31;
    const int t0   = blockIdx.x << 7;
    const int NS   = (KIND == 0) ? 16 : 32;
    constexpr int AR  = (KIND == 0) ? A0ROWB : A1ROWB;
    constexpr int STB = (KIND == 0) ? STB0 : STB1;
    constexpr uint32_t HALF = 128u * (uint32_t)AR;

    float* scp = (float*)(smem + NPIPE * STB1);
    float* bcp = scp + 256;
    if (KIND == 1) {
        int b = t0 >> 12;
        float mu = g_mean[b], rho = g_rstd[b];
        int c = tid;
        float ga = gamma[c], be = beta[c];
        scp[c] = rho * ga;
        bcp[c] = be - mu * rho * ga;
    }

    int o0, wsel = 0;
    if (KIND == 0) { wsel = blockIdx.y >> 1; o0 = (blockIdx.y & 1) << 7; }
    else           { o0 = blockIdx.y << 7; }

    const int wm = wid & 1;
    const int wn = wid >> 1;

    auto load_stage = [&](int s) {
        const __half *Ah, *Al, *Wf;
        int k0;
        if (KIND == 0) {
            Ah = g_xh; Al = g_xl;
            Wf = wsel ? g_wvf : g_Gf;
            k0 = s << 4;
        } else {
            Al = nullptr;
            if (s < 16) { Ah = g_xh;  Wf = g_wof; k0 = s << 4; }
            else        { Ah = g_vtf; Wf = g_wzf; k0 = (s - 16) << 4; }
        }
        const uint32_t buf = sbase + (uint32_t)(s & (NPIPE - 1)) * (uint32_t)STB;
        if (KIND == 0) {
#pragma unroll
            for (int i = 0; i < 3; i++) {
                int idx = tid + (i << 8);
                if (idx < 512) {
                    int r = idx >> 2, ch = idx & 3;
                    if (!(wsel && ch >= 2)) {
                        const __half* src = ((ch < 2) ? Ah : Al) + (size_t)(t0 + r) * NC + k0 + ((ch & 1) << 3);
                        cpa16(buf + (uint32_t)(r * AR + (ch << 4)), src);
                    }
                } else {
                    int j = idx - 512;
                    int r = j >> 1, ch = j & 1;
                    const __half* src = Wf + (size_t)(o0 + r) * NC + k0 + (ch << 3);
                    cpa16(buf + HALF + (uint32_t)(r * WROWB + (ch << 4)), src);
                }
            }
        } else {
#pragma unroll
            for (int i = 0; i < 2; i++) {
                int idx = tid + (i << 8);
                if (idx < 256) {
                    int r = idx >> 1, ch = idx & 1;
                    const __half* src = Ah + (size_t)(t0 + r) * NC + k0 + (ch << 3);
                    cpa16(buf + (uint32_t)(r * AR + (ch << 4)), src);
                } else {
                    int j = idx - 256;
                    int r = j >> 1, ch = j & 1;
                    const __half* src = Wf + (size_t)(o0 + r) * NC + k0 + (ch << 3);
                    cpa16(buf + HALF + (uint32_t)(r * WROWB + (ch << 4)), src);
                }
            }
        }
        asm volatile("cp.async.commit_group;" ::: "memory");
    };

    float acc[4][4][4];
#pragma unroll
    for (int a = 0; a < 4; a++)
#pragma unroll
        for (int b = 0; b < 4; b++)
#pragma unroll
            for (int c = 0; c < 4; c++) acc[a][b][c] = 0.f;

    const int rq = lane >> 2;
    const int p4 = (lane & 3) << 2;

    load_stage(0);
    load_stage(1);
    load_stage(2);

    for (int s = 0; s < NS; s++) {
        int rem = NS - 1 - s;
        if (rem >= 2)      asm volatile("cp.async.wait_group 2;" ::: "memory");
        else if (rem == 1) asm volatile("cp.async.wait_group 1;" ::: "memory");
        else               asm volatile("cp.async.wait_group 0;" ::: "memory");
        __syncthreads();
        if (s + 3 < NS) load_stage(s + 3);

        const uint32_t bufA = sbase + (uint32_t)(s & (NPIPE - 1)) * (uint32_t)STB;
        const uint32_t bufW = bufA + HALF;

        uint32_t ah[4][4], al[4][4], bf[4][2];
#pragma unroll
        for (int mt = 0; mt < 4; mt++) {
            uint32_t base = bufA + (uint32_t)((wm * 64 + mt * 16 + rq) * AR + p4);
            ah[mt][0] = lds32v(base);
            ah[mt][1] = lds32v(base + 8 * AR);
            ah[mt][2] = lds32v(base + 16);
            ah[mt][3] = lds32v(base + 8 * AR + 16);
            if (KIND == 0 && !wsel) {
                al[mt][0] = lds32v(base + 32);
                al[mt][1] = lds32v(base + 8 * AR + 32);
                al[mt][2] = lds32v(base + 48);
                al[mt][3] = lds32v(base + 8 * AR + 48);
            }
        }
        if (KIND == 1 && s >= 16) {
            int cb = ((s - 16) << 4) + ((lane & 3) << 1);
#pragma unroll
            for (int j = 0; j < 4; j++) {
                int c = cb + ((j >> 1) & 1) * 8;
                float s0 = scp[c], s1 = scp[c + 1];
                float b0 = bcp[c], b1 = bcp[c + 1];
#pragma unroll
                for (int mt = 0; mt < 4; mt++) {
                    __half2 h = *(__half2*)&ah[mt][j];
                    float v0 = fmaxf(fmaf(__half2float(h.x), s0, b0), 0.f);
                    float v1 = fmaxf(fmaf(__half2float(h.y), s1, b1), 0.f);
                    __half2 r = __floats2half2_rn(v0, v1);
                    ah[mt][j] = *(uint32_t*)&r;
                }
            }
        }
#pragma unroll
        for (int nt = 0; nt < 4; nt++) {
            uint32_t base = bufW + (uint32_t)((wn * 32 + nt * 8 + rq) * WROWB + p4);
            bf[nt][0] = lds32v(base);
            bf[nt][1] = lds32v(base + 16);
        }
#pragma unroll
        for (int mt = 0; mt < 4; mt++)
#pragma unroll
            for (int nt = 0; nt < 4; nt++) {
                MMAF16(acc[mt][nt], ah[mt], bf[nt]);
                if (KIND == 0 && !wsel) MMAF16(acc[mt][nt], al[mt], bf[nt]);
            }
    }

    const int fr = lane >> 2;
    const int fc = (lane & 3) * 2;
#pragma unroll
    for (int mt = 0; mt < 4; mt++) {
#pragma unroll
        for (int nt = 0; nt < 4; nt++) {
            int r = wm * 64 + mt * 16 + fr;
            int c = wn * 32 + nt * 8 + fc;
            float d0 = acc[mt][nt][0], d1 = acc[mt][nt][1];
            float d2 = acc[mt][nt][2], d3 = acc[mt][nt][3];
            if (KIND == 0) {
                __half* dst = wsel ? g_vf : g_zf;
                __half2 h01; h01.x = __float2half(d0); h01.y = __float2half(d1);
                __half2 h23; h23.x = __float2half(d2); h23.y = __float2half(d3);
                *(__half2*)(dst + (size_t)(t0 + r) * NC + o0 + c)     = h01;
                *(__half2*)(dst + (size_t)(t0 + r + 8) * NC + o0 + c) = h23;
            } else {
                const int b = t0 >> 12;
                int l = (t0 & 4095) + r;
                outf[((size_t)(b * NOUT + o0 + c))     * NL + l] = d0;
                outf[((size_t)(b * NOUT + o0 + c + 1)) * NL + l] = d1;
                outf[((size_t)(b * NOUT + o0 + c))     * NL + l + 8] = d2;
                outf[((size_t)(b * NOUT + o0 + c + 1)) * NL + l + 8] = d3;
            }
        }
    }
}

// ================= K: tensorized per-l batch attention (512 threads, ldmatrix) =================
// smem: QH 0 (64x528), QL 33792, K 67584, S 101376 (fp32 [64][68], reused as GN accum),
//       AH 118784 (64x144, single fp16 att), V 128000 (2 x 64x144)
#define OF_QH 0
#define OF_QL 33792
#define OF_K  67584
#define OF_S  101376
#define OF_AH 118784
#define OF_V  128000
#define SM_ATTN_BYTES (OF_V + 2 * 9216)   // 146432

__global__ __launch_bounds__(512) void k_attn()
{
    extern __shared__ __align__(128) char smc[];
    const uint32_t S0 = smem_to_u32(smc);
    float* smf = (float*)smc;
    const int l = blockIdx.x;
    const int tid = threadIdx.x;
    const int wid = tid >> 5, lane = tid & 31;
    const int rq = lane >> 2, p4 = (lane & 3) << 2;
    const int m0 = (wid & 3) * 16;        // 4 m-warps
    const int n0 = (wid >> 2) * 16;       // 4 n-warps
    const int lm16 = lane & 15;           // ldmatrix row select
    const int lk16 = (lane >> 4) << 4;    // ldmatrix k-half byte offset

    // ---- load Q(x hi/lo) and K(z single) ----
    for (int idx = tid; idx < 2048; idx += 512) {
        int row = idx >> 5, ch = idx & 31;
        size_t g = ((size_t)row * NL + l) * NC + ch * 8;
        uint32_t so = (uint32_t)(row * 528 + ch * 16);
        cpa16(S0 + OF_QH + so, g_xh + g);
        cpa16(S0 + OF_QL + so, g_xl + g);
        cpa16(S0 + OF_K  + so, g_zf + g);
    }
    for (int idx = tid; idx < 512; idx += 512) {
        int d = idx >> 3, ch = idx & 7;
        size_t g = ((size_t)d * NL + l) * NC + ch * 8;
        cpa16(S0 + OF_V + (uint32_t)(d * 144 + ch * 16), g_vf + g);
    }
    asm volatile("cp.async.commit_group;" ::: "memory");
    asm volatile("cp.async.wait_group 0;" ::: "memory");
    __syncthreads();

    // ---- scores S[b][d] = (x_b . z_d)/16 ; 2-term one-sided split ----
    float acc[2][4];
#pragma unroll
    for (int i = 0; i < 2; i++)
#pragma unroll
        for (int j = 0; j < 4; j++) acc[i][j] = 0.f;

#pragma unroll
    for (int kk = 0; kk < 16; kk++) {
        uint32_t aaddr = S0 + OF_QH + (uint32_t)((m0 + lm16) * 528 + kk * 32 + lk16);
        uint32_t ah[4], al[4];
        LDSM_X4(ah[0], ah[1], ah[2], ah[3], aaddr);
        LDSM_X4(al[0], al[1], al[2], al[3], aaddr + (OF_QL - OF_QH));
#pragma unroll
        for (int nt = 0; nt < 2; nt++) {
            uint32_t bbase = S0 + OF_K + (uint32_t)((n0 + nt * 8 + rq) * 528 + kk * 32 + p4);
            uint32_t bf[2];
            bf[0] = lds32v(bbase);
            bf[1] = lds32v(bbase + 16);
            MMAF16(acc[nt], ah, bf);
            MMAF16(acc[nt], al, bf);
        }
    }
#pragma unroll
    for (int nt = 0; nt < 2; nt++) {
        int r = m0 + rq;
        int c = n0 + nt * 8 + (lane & 3) * 2;
        *(float2*)&smf[(OF_S >> 2) + r * 68 + c]       = make_float2(acc[nt][0] * 0.0625f, acc[nt][1] * 0.0625f);
        *(float2*)&smf[(OF_S >> 2) + (r + 8) * 68 + c] = make_float2(acc[nt][2] * 0.0625f, acc[nt][3] * 0.0625f);
    }
    __syncthreads();

    // ---- softmax over d, write att as single fp16 ----
    if (tid < 64) {
        float* row = &smf[(OF_S >> 2) + tid * 68];
        float m = row[0];
        for (int d = 1; d < 64; d++) m = fmaxf(m, row[d]);
        float s = 0.f;
        float e[64];
        for (int d = 0; d < 64; d++) { e[d] = __expf(row[d] - m); s += e[d]; }
        float inv = 1.f / s;
        for (int d = 0; d < 64; d += 2) {
            __half2 hh = __floats2half2_rn(e[d] * inv, e[d + 1] * inv);
            *(__half2*)(smc + OF_AH + tid * 144 + d * 2) = hh;
        }
        smf[(OF_S >> 2) + tid] = 0.f;
        smf[(OF_S >> 2) + 64 + tid] = 0.f;
    }

    // ---- AV: virt[b][c] = sum_d att[b][d] v[d][c], chunked over c ----
    float gs0 = 0.f, gss0 = 0.f, gs1 = 0.f, gss1 = 0.f;

    for (int cc = 0; cc < 4; cc++) {
        __syncthreads();
        if (cc < 3) {
            int nb = (cc + 1) & 1;
            for (int idx = tid; idx < 512; idx += 512) {
                int d = idx >> 3, ch = idx & 7;
                size_t g = ((size_t)d * NL + l) * NC + (cc + 1) * 64 + ch * 8;
                cpa16(S0 + OF_V + (uint32_t)(nb * 9216 + d * 144 + ch * 16), g_vf + g);
            }
            asm volatile("cp.async.commit_group;" ::: "memory");
            asm volatile("cp.async.wait_group 1;" ::: "memory");
        } else {
            asm volatile("cp.async.wait_group 0;" ::: "memory");
        }
        __syncthreads();

        const uint32_t VB = S0 + OF_V + (uint32_t)((cc & 1) * 9216);

        float av[2][4];
#pragma unroll
        for (int i = 0; i < 2; i++)
#pragma unroll
            for (int j = 0; j < 4; j++) av[i][j] = 0.f;

#pragma unroll
        for (int k = 0; k < 4; k++) {
            uint32_t aaddr = S0 + OF_AH + (uint32_t)((m0 + lm16) * 144 + k * 32 + lk16);
            uint32_t ah[4];
            LDSM_X4(ah[0], ah[1], ah[2], ah[3], aaddr);
#pragma unroll
            for (int nt = 0; nt < 2; nt++) {
                // B from V[d][c] row-major via ldmatrix.trans: rows = d (k-dim)
                uint32_t baddr = VB + (uint32_t)((k * 16 + lm16) * 144 + (n0 + nt * 8) * 2);
                uint32_t bf[2];
                LDSM_X2T(bf[0], bf[1], baddr);
                MMAF16(av[nt], ah, bf);
            }
        }
#pragma unroll
        for (int nt = 0; nt < 2; nt++) {
            int b0r = m0 + rq;
            int c = cc * 64 + n0 + nt * 8 + (lane & 3) * 2;
            float v0 = av[nt][0], v1 = av[nt][1], v2 = av[nt][2], v3 = av[nt][3];
            __half2 h01 = __floats2half2_rn(v0, v1);
            __half2 h23 = __floats2half2_rn(v2, v3);
            *(__half2*)(g_vtf + ((size_t)b0r * NL + l) * NC + c)       = h01;
            *(__half2*)(g_vtf + ((size_t)(b0r + 8) * NL + l) * NC + c) = h23;
            gs0  += v0 + v1;
            gss0 += v0 * v0 + v1 * v1;
            gs1  += v2 + v3;
            gss1 += v2 * v2 + v3 * v3;
        }
    }

    gs0  += __shfl_xor_sync(0xffffffffu, gs0, 1);  gs0  += __shfl_xor_sync(0xffffffffu, gs0, 2);
    gss0 += __shfl_xor_sync(0xffffffffu, gss0, 1); gss0 += __shfl_xor_sync(0xffffffffu, gss0, 2);
    gs1  += __shfl_xor_sync(0xffffffffu, gs1, 1);  gs1  += __shfl_xor_sync(0xffffffffu, gs1, 2);
    gss1 += __shfl_xor_sync(0xffffffffu, gss1, 1); gss1 += __shfl_xor_sync(0xffffffffu, gss1, 2);
    if ((lane & 3) == 0) {
        atomicAdd(&smf[(OF_S >> 2) + m0 + rq], gs0);
        atomicAdd(&smf[(OF_S >> 2) + 64 + m0 + rq], gss0);
        atomicAdd(&smf[(OF_S >> 2) + m0 + rq + 8], gs1);
        atomicAdd(&smf[(OF_S >> 2) + 64 + m0 + rq + 8], gss1);
    }
    __syncthreads();
    if (tid < 64) {
        atomicAdd(&g_psum[tid],   smf[(OF_S >> 2) + tid]);
        atomicAdd(&g_psumsq[tid], smf[(OF_S >> 2) + 64 + tid]);
    }
}

// ================= K: stats =================
__global__ void k_stats()
{
    int b = threadIdx.x;
    if (b < NB) {
        const float n = (float)NC * (float)NL;
        float mean = g_psum[b] / n;
        float var  = g_psumsq[b] / n - mean * mean;
        if (var < 0.f) var = 0.f;
        g_mean[b] = mean;
        g_rstd[b] = rsqrtf(var + 1e-5f);
    }
}

// ================= launch =================
extern "C" void kernel_launch(void* const* d_in, const int* in_sizes, int n_in,
                              void* d_out, int out_size)
{
    const float* x     = (const float*)d_in[0];
    const float* Wq    = (const float*)d_in[1];
    const float* Wk    = (const float*)d_in[2];
    const float* Wv    = (const float*)d_in[3];
    const float* Wc    = (const float*)d_in[4];
    const float* Wout  = (const float*)d_in[5];
    const float* gamma = (const float*)d_in[6];
    const float* beta  = (const float*)d_in[7];
    float* out = (float*)d_out;

    cudaFuncSetAttribute(k_attn,    cudaFuncAttributeMaxDynamicSharedMemorySize, SM_ATTN_BYTES);
    cudaFuncSetAttribute(k_gemm<0>, cudaFuncAttributeMaxDynamicSharedMemorySize, SMEM_GEMM0);
    cudaFuncSetAttribute(k_gemm<1>, cudaFuncAttributeMaxDynamicSharedMemorySize, SMEM_GEMM1);

    k_wprep<<<161, 256>>>(Wq, Wk, Wout, Wc, Wv);
    k_prep0<<<dim3(64, 4, 64), 256>>>(x);
    k_gemm<0><<<dim3(2048, 4), 256, SMEM_GEMM0>>>(nullptr, nullptr, nullptr); // z (split), v (single)
    k_attn<<<NL, 512, SM_ATTN_BYTES>>>();
    k_stats<<<1, 64>>>();
    k_gemm<1><<<dim3(2048, 2), 256, SMEM_GEMM1>>>(out, gamma, beta);          // out = Wout x + Wz gn
}

// round 17
// speedup vs baseline: 1.9023x; 1.0072x over previous
#include <cuda_runtime.h>
#include <cuda_fp16.h>
#include <cstdint>

#define NB   64
#define NC   256
#define NL   4096
#define NOUT 256
#define NTOK (NB * NL)   // 262144 tokens

// ================= helpers =================
__device__ __forceinline__ uint32_t smem_to_u32(const void* p) {
    uint32_t a;
    asm("{ .reg .u64 t; cvta.to.shared.u64 t, %1; cvt.u32.u64 %0, t; }" : "=r"(a) : "l"(p));
    return a;
}
__device__ __forceinline__ void cpa16(uint32_t s, const void* g) {
    asm volatile("cp.async.cg.shared.global [%0], [%1], 16;" :: "r"(s), "l"(g) : "memory");
}
__device__ __forceinline__ uint32_t lds32v(uint32_t a) {
    uint32_t v;
    asm volatile("ld.shared.b32 %0, [%1];" : "=r"(v) : "r"(a) : "memory");
    return v;
}
#define LDSM_X4(r0, r1, r2, r3, addr) \
    asm volatile("ldmatrix.sync.aligned.m8n8.x4.shared.b16 {%0,%1,%2,%3}, [%4];" \
        : "=r"(r0), "=r"(r1), "=r"(r2), "=r"(r3) : "r"(addr))
#define LDSM_X2T(r0, r1, addr) \
    asm volatile("ldmatrix.sync.aligned.m8n8.x2.trans.shared.b16 {%0,%1}, [%2];" \
        : "=r"(r0), "=r"(r1) : "r"(addr))
#define MMAF16(d, a, b) \
    asm volatile("mma.sync.aligned.m16n8k16.row.col.f32.f16.f16.f32 " \
        "{%0,%1,%2,%3},{%4,%5,%6,%7},{%8,%9},{%0,%1,%2,%3};" \
        : "+f"((d)[0]), "+f"((d)[1]), "+f"((d)[2]), "+f"((d)[3]) \
        : "r"((a)[0]), "r"((a)[1]), "r"((a)[2]), "r"((a)[3]), "r"((b)[0]), "r"((b)[1]))
#define CPWAIT(n) asm volatile("cp.async.wait_group %0;" :: "n"(n) : "memory")

// ================= scratch (device globals; referenced ONLY in device code) =================
__device__ __align__(256) __half g_xh  [(long long)NTOK * NC];
__device__ __align__(256) __half g_xl  [(long long)NTOK * NC];
__device__ __align__(256) __half g_zf  [(long long)NTOK * NC];
__device__ __align__(256) __half g_vf  [(long long)NTOK * NC];
__device__ __align__(256) __half g_vtf [(long long)NTOK * NC];   // virt (fp16)
__device__ __align__(256) __half g_Gf [NC * NC];
__device__ __align__(256) __half g_wvf[NC * NC];
__device__ __align__(256) __half g_wof[NC * NC];
__device__ __align__(256) __half g_wzf[NC * NC];
__device__ float g_psum[NB], g_psumsq[NB], g_mean[NB], g_rstd[NB];

// ================= K: fused weight prep =================
__global__ __launch_bounds__(256) void k_wprep(
    const float* __restrict__ Wq, const float* __restrict__ Wk,
    const float* __restrict__ Wo, const float* __restrict__ Wc,
    const float* __restrict__ Wv)
{
    const int bx = blockIdx.x;
    const int tid = threadIdx.x;

    if (bx >= 160) {
        if (tid < NB) { g_psum[tid] = 0.f; g_psumsq[tid] = 0.f; }
        return;
    }
    if (bx >= 32) {
        int gid = (bx - 32) * 256 + tid;
        int arr = gid >> 14;
        int off = (gid & 16383) * 4;
        const float* src = (arr == 0) ? Wv : Wo;
        __half* dst = (arr == 0) ? g_wvf : g_wof;
        float4 v = *(const float4*)(src + off);
        __half2 h0; h0.x = __float2half(v.x); h0.y = __float2half(v.y);
        __half2 h1; h1.x = __float2half(v.z); h1.y = __float2half(v.w);
        *(__half2*)(dst + off)     = h0;
        *(__half2*)(dst + off + 2) = h1;
        return;
    }

    __shared__ float sA[16][68], sB[16][68];
    const bool isG = (bx < 16);
    const int bb = isG ? bx : bx - 16;
    const int e0 = (bb & 3) << 6;
    const int f0 = (bb >> 2) << 6;
    const int tx = tid & 15, ty = tid >> 4;

    float acc[4][4];
#pragma unroll
    for (int i = 0; i < 4; i++)
#pragma unroll
        for (int j = 0; j < 4; j++) acc[i][j] = 0.f;

    for (int k0 = 0; k0 < NC; k0 += 16) {
#pragma unroll
        for (int i = 0; i < 4; i++) {
            int r = (tid >> 6) + i * 4, col = tid & 63;
            if (isG) {
                sA[r][col] = Wq[(size_t)(k0 + r) * NC + e0 + col];
                sB[r][col] = Wk[(size_t)(k0 + r) * NC + f0 + col];
            } else {
                sA[r][col] = Wo[(size_t)(e0 + col) * NC + k0 + r];
                sB[r][col] = Wc[(size_t)(k0 + r) * NC + f0 + col];
            }
        }
        __syncthreads();
#pragma unroll
        for (int kk = 0; kk < 16; kk++) {
            float a[4], b2[4];
#pragma unroll
            for (int i = 0; i < 4; i++) { a[i] = sA[kk][ty * 4 + i]; b2[i] = sB[kk][tx * 4 + i]; }
#pragma unroll
            for (int i = 0; i < 4; i++)
#pragma unroll
                for (int j = 0; j < 4; j++) acc[i][j] = fmaf(a[i], b2[j], acc[i][j]);
        }
        __syncthreads();
    }
    __half* dst = isG ? g_Gf : g_wzf;
#pragma unroll
    for (int i = 0; i < 4; i++)
#pragma unroll
        for (int j = 0; j < 4; j++)
            dst[(e0 + ty * 4 + i) * NC + f0 + tx * 4 + j] = __float2half(acc[i][j]);
}

// ================= K: transpose x -> fp16 hi/lo split (token-major) =================
__global__ __launch_bounds__(256) void k_prep0(const float* __restrict__ x)
{
    __shared__ float tile[64][65];
    const int b  = blockIdx.z;
    const int l0 = blockIdx.x << 6;
    const int c0 = blockIdx.y << 6;
    const int tid = threadIdx.x;
    const int tx = tid & 63, ty = tid >> 6;

    const float* xp = x + (size_t)b * NC * NL + (size_t)c0 * NL + l0;
#pragma unroll
    for (int i = 0; i < 16; i++) {
        int r = i * 4 + ty;
        tile[r][tx] = xp[(size_t)r * NL + tx];
    }
    __syncthreads();
#pragma unroll
    for (int i = 0; i < 16; i++) {
        int lr = i * 4 + ty;
        float v = tile[tx][lr];
        size_t idx = ((size_t)(b * NL + l0 + lr)) * NC + c0 + tx;
        __half h = __float2half(v);
        g_xh[idx] = h;
        g_xl[idx] = __float2half(v - __half2float(h));
    }
}

// ================= K: fp16 GEMM, 4-stage pipeline =================
#define WROWB   48
#define A0ROWB  80
#define A1ROWB  48
#define STB0    (128 * A0ROWB + 128 * WROWB)   // 16384
#define STB1    (128 * A1ROWB + 128 * WROWB)   // 12288
#define NPIPE   4
#define SMEM_GEMM0 (NPIPE * STB0)              // 65536
#define SMEM_GEMM1 (NPIPE * STB1 + 2048)       // 51200

template<int KIND>
__global__ __launch_bounds__(256) void k_gemm(
    float* __restrict__ outf,
    const float* __restrict__ gamma, const float* __restrict__ beta)
{
    extern __shared__ __align__(128) char smem[];
    const uint32_t sbase = smem_to_u32(smem);
    const int tid  = threadIdx.x;
    const int wid  = tid >> 5;
    const int lane = tid & 31;
    const int t0   = blockIdx.x << 7;
    const int NS   = (KIND == 0) ? 16 : 32;
    constexpr int AR  = (KIND == 0) ? A0ROWB : A1ROWB;
    constexpr int STB = (KIND == 0) ? STB0 : STB1;
    constexpr uint32_t HALF = 128u * (uint32_t)AR;

    float* scp = (float*)(smem + NPIPE * STB1);
    float* bcp = scp + 256;
    if (KIND == 1) {
        int b = t0 >> 12;
        float mu = g_mean[b], rho = g_rstd[b];
        int c = tid;
        float ga = gamma[c], be = beta[c];
        scp[c] = rho * ga;
        bcp[c] = be - mu * rho * ga;
    }

    int o0, wsel = 0;
    if (KIND == 0) { wsel = blockIdx.y >> 1; o0 = (blockIdx.y & 1) << 7; }
    else           { o0 = blockIdx.y << 7; }

    const int wm = wid & 1;
    const int wn = wid >> 1;

    auto load_stage = [&](int s) {
        const __half *Ah, *Al, *Wf;
        int k0;
        if (KIND == 0) {
            Ah = g_xh; Al = g_xl;
            Wf = wsel ? g_wvf : g_Gf;
            k0 = s << 4;
        } else {
            Al = nullptr;
            if (s < 16) { Ah = g_xh;  Wf = g_wof; k0 = s << 4; }
            else        { Ah = g_vtf; Wf = g_wzf; k0 = (s - 16) << 4; }
        }
        const uint32_t buf = sbase + (uint32_t)(s & (NPIPE - 1)) * (uint32_t)STB;
        if (KIND == 0) {
#pragma unroll
            for (int i = 0; i < 3; i++) {
                int idx = tid + (i << 8);
                if (idx < 512) {
                    int r = idx >> 2, ch = idx & 3;
                    if (!(wsel && ch >= 2)) {
                        const __half* src = ((ch < 2) ? Ah : Al) + (size_t)(t0 + r) * NC + k0 + ((ch & 1) << 3);
                        cpa16(buf + (uint32_t)(r * AR + (ch << 4)), src);
                    }
                } else {
                    int j = idx - 512;
                    int r = j >> 1, ch = j & 1;
                    const __half* src = Wf + (size_t)(o0 + r) * NC + k0 + (ch << 3);
                    cpa16(buf + HALF + (uint32_t)(r * WROWB + (ch << 4)), src);
                }
            }
        } else {
#pragma unroll
            for (int i = 0; i < 2; i++) {
                int idx = tid + (i << 8);
                if (idx < 256) {
                    int r = idx >> 1, ch = idx & 1;
                    const __half* src = Ah + (size_t)(t0 + r) * NC + k0 + (ch << 3);
                    cpa16(buf + (uint32_t)(r * AR + (ch << 4)), src);
                } else {
                    int j = idx - 256;
                    int r = j >> 1, ch = j & 1;
                    const __half* src = Wf + (size_t)(o0 + r) * NC + k0 + (ch << 3);
                    cpa16(buf + HALF + (uint32_t)(r * WROWB + (ch << 4)), src);
                }
            }
        }
        asm volatile("cp.async.commit_group;" ::: "memory");
    };

    float acc[4][4][4];
#pragma unroll
    for (int a = 0; a < 4; a++)
#pragma unroll
        for (int b = 0; b < 4; b++)
#pragma unroll
            for (int c = 0; c < 4; c++) acc[a][b][c] = 0.f;

    const int rq = lane >> 2;
    const int p4 = (lane & 3) << 2;

    load_stage(0);
    load_stage(1);
    load_stage(2);

    for (int s = 0; s < NS; s++) {
        int rem = NS - 1 - s;
        if (rem >= 2)      CPWAIT(2);
        else if (rem == 1) CPWAIT(1);
        else               CPWAIT(0);
        __syncthreads();
        if (s + 3 < NS) load_stage(s + 3);

        const uint32_t bufA = sbase + (uint32_t)(s & (NPIPE - 1)) * (uint32_t)STB;
        const uint32_t bufW = bufA + HALF;

        uint32_t ah[4][4], al[4][4], bf[4][2];
#pragma unroll
        for (int mt = 0; mt < 4; mt++) {
            uint32_t base = bufA + (uint32_t)((wm * 64 + mt * 16 + rq) * AR + p4);
            ah[mt][0] = lds32v(base);
            ah[mt][1] = lds32v(base + 8 * AR);
            ah[mt][2] = lds32v(base + 16);
            ah[mt][3] = lds32v(base + 8 * AR + 16);
            if (KIND == 0 && !wsel) {
                al[mt][0] = lds32v(base + 32);
                al[mt][1] = lds32v(base + 8 * AR + 32);
                al[mt][2] = lds32v(base + 48);
                al[mt][3] = lds32v(base + 8 * AR + 48);
            }
        }
        if (KIND == 1 && s >= 16) {
            int cb = ((s - 16) << 4) + ((lane & 3) << 1);
#pragma unroll
            for (int j = 0; j < 4; j++) {
                int c = cb + ((j >> 1) & 1) * 8;
                float s0 = scp[c], s1 = scp[c + 1];
                float b0 = bcp[c], b1 = bcp[c + 1];
#pragma unroll
                for (int mt = 0; mt < 4; mt++) {
                    __half2 h = *(__half2*)&ah[mt][j];
                    float v0 = fmaxf(fmaf(__half2float(h.x), s0, b0), 0.f);
                    float v1 = fmaxf(fmaf(__half2float(h.y), s1, b1), 0.f);
                    __half2 r = __floats2half2_rn(v0, v1);
                    ah[mt][j] = *(uint32_t*)&r;
                }
            }
        }
#pragma unroll
        for (int nt = 0; nt < 4; nt++) {
            uint32_t base = bufW + (uint32_t)((wn * 32 + nt * 8 + rq) * WROWB + p4);
            bf[nt][0] = lds32v(base);
            bf[nt][1] = lds32v(base + 16);
        }
#pragma unroll
        for (int mt = 0; mt < 4; mt++)
#pragma unroll
            for (int nt = 0; nt < 4; nt++) {
                MMAF16(acc[mt][nt], ah[mt], bf[nt]);
                if (KIND == 0 && !wsel) MMAF16(acc[mt][nt], al[mt], bf[nt]);
            }
    }

    const int fr = lane >> 2;
    const int fc = (lane & 3) * 2;
#pragma unroll
    for (int mt = 0; mt < 4; mt++) {
#pragma unroll
        for (int nt = 0; nt < 4; nt++) {
            int r = wm * 64 + mt * 16 + fr;
            int c = wn * 32 + nt * 8 + fc;
            float d0 = acc[mt][nt][0], d1 = acc[mt][nt][1];
            float d2 = acc[mt][nt][2], d3 = acc[mt][nt][3];
            if (KIND == 0) {
                __half* dst = wsel ? g_vf : g_zf;
                __half2 h01; h01.x = __float2half(d0); h01.y = __float2half(d1);
                __half2 h23; h23.x = __float2half(d2); h23.y = __float2half(d3);
                *(__half2*)(dst + (size_t)(t0 + r) * NC + o0 + c)     = h01;
                *(__half2*)(dst + (size_t)(t0 + r + 8) * NC + o0 + c) = h23;
            } else {
                const int b = t0 >> 12;
                int l = (t0 & 4095) + r;
                outf[((size_t)(b * NOUT + o0 + c))     * NL + l] = d0;
                outf[((size_t)(b * NOUT + o0 + c + 1)) * NL + l] = d1;
                outf[((size_t)(b * NOUT + o0 + c))     * NL + l + 8] = d2;
                outf[((size_t)(b * NOUT + o0 + c + 1)) * NL + l + 8] = d3;
            }
        }
    }
}

// ================= K: attention, fully streamed loads (8 commit groups) =================
// smem: QH 0 (64x528), QL 33792, K 67584, S 101376 (fp32 [64][68], GN accum reuse),
//       AH 118784 (64x144), V 128000 (4 x 64x144)
#define OF_QH 0
#define OF_QL 33792
#define OF_K  67584
#define OF_S  101376
#define OF_AH 118784
#define OF_V  128000
#define SM_ATTN_BYTES (OF_V + 4 * 9216)   // 164864

__global__ __launch_bounds__(512) void k_attn()
{
    extern __shared__ __align__(128) char smc[];
    const uint32_t S0 = smem_to_u32(smc);
    float* smf = (float*)smc;
    const int l = blockIdx.x;
    const int tid = threadIdx.x;
    const int wid = tid >> 5, lane = tid & 31;
    const int rq = lane >> 2, p4 = (lane & 3) << 2;
    const int m0 = (wid & 3) * 16;
    const int n0 = (wid >> 2) * 16;
    const int lm16 = lane & 15;
    const int lk16 = (lane >> 4) << 4;

    // ---- issue ALL loads up-front: Q/K column-quarters (groups 0-3), V chunks (groups 4-7) ----
    {
        int row = tid >> 3, ch = tid & 7;   // 512 threads = 64 rows x 8 chunks
#pragma unroll
        for (int q = 0; q < 4; q++) {
            size_t g = ((size_t)row * NL + l) * NC + q * 64 + ch * 8;
            uint32_t so = (uint32_t)(row * 528 + q * 128 + ch * 16);
            cpa16(S0 + OF_QH + so, g_xh + g);
            cpa16(S0 + OF_QL + so, g_xl + g);
            cpa16(S0 + OF_K  + so, g_zf + g);
            asm volatile("cp.async.commit_group;" ::: "memory");
        }
#pragma unroll
        for (int cc = 0; cc < 4; cc++) {
            size_t g = ((size_t)row * NL + l) * NC + cc * 64 + ch * 8;
            cpa16(S0 + OF_V + (uint32_t)(cc * 9216 + row * 144 + ch * 16), g_vf + g);
            asm volatile("cp.async.commit_group;" ::: "memory");
        }
    }

    // ---- scores S[b][d] = (x_b . z_d)/16, quarter-pipelined ----
    float acc[2][4];
#pragma unroll
    for (int i = 0; i < 2; i++)
#pragma unroll
        for (int j = 0; j < 4; j++) acc[i][j] = 0.f;

#pragma unroll
    for (int q = 0; q < 4; q++) {
        switch (q) {
            case 0: CPWAIT(7); break;
            case 1: CPWAIT(6); break;
            case 2: CPWAIT(5); break;
            default: CPWAIT(4); break;
        }
        __syncthreads();
#pragma unroll
        for (int j = 0; j < 4; j++) {
            int kk = q * 4 + j;
            uint32_t aaddr = S0 + OF_QH + (uint32_t)((m0 + lm16) * 528 + kk * 32 + lk16);
            uint32_t ah[4], al[4];
            LDSM_X4(ah[0], ah[1], ah[2], ah[3], aaddr);
            LDSM_X4(al[0], al[1], al[2], al[3], aaddr + (OF_QL - OF_QH));
#pragma unroll
            for (int nt = 0; nt < 2; nt++) {
                uint32_t bbase = S0 + OF_K + (uint32_t)((n0 + nt * 8 + rq) * 528 + kk * 32 + p4);
                uint32_t bf[2];
                bf[0] = lds32v(bbase);
                bf[1] = lds32v(bbase + 16);
                MMAF16(acc[nt], ah, bf);
                MMAF16(acc[nt], al, bf);
            }
        }
    }
#pragma unroll
    for (int nt = 0; nt < 2; nt++) {
        int r = m0 + rq;
        int c = n0 + nt * 8 + (lane & 3) * 2;
        *(float2*)&smf[(OF_S >> 2) + r * 68 + c]       = make_float2(acc[nt][0] * 0.0625f, acc[nt][1] * 0.0625f);
        *(float2*)&smf[(OF_S >> 2) + (r + 8) * 68 + c] = make_float2(acc[nt][2] * 0.0625f, acc[nt][3] * 0.0625f);
    }
    __syncthreads();

    // ---- softmax over d, write att as single fp16 ----
    if (tid < 64) {
        float* row = &smf[(OF_S >> 2) + tid * 68];
        float m = row[0];
        for (int d = 1; d < 64; d++) m = fmaxf(m, row[d]);
        float s = 0.f;
        float e[64];
        for (int d = 0; d < 64; d++) { e[d] = __expf(row[d] - m); s += e[d]; }
        float inv = 1.f / s;
        for (int d = 0; d < 64; d += 2) {
            __half2 hh = __floats2half2_rn(e[d] * inv, e[d + 1] * inv);
            *(__half2*)(smc + OF_AH + tid * 144 + d * 2) = hh;
        }
        smf[(OF_S >> 2) + tid] = 0.f;
        smf[(OF_S >> 2) + 64 + tid] = 0.f;
    }

    // ---- AV: virt[b][c] = sum_d att[b][d] v[d][c], 4 prefetched chunks ----
    float gs0 = 0.f, gss0 = 0.f, gs1 = 0.f, gss1 = 0.f;

#pragma unroll
    for (int cc = 0; cc < 4; cc++) {
        switch (cc) {
            case 0: CPWAIT(3); break;
            case 1: CPWAIT(2); break;
            case 2: CPWAIT(1); break;
            default: CPWAIT(0); break;
        }
        __syncthreads();

        const uint32_t VB = S0 + OF_V + (uint32_t)(cc * 9216);

        float av[2][4];
#pragma unroll
        for (int i = 0; i < 2; i++)
#pragma unroll
            for (int j = 0; j < 4; j++) av[i][j] = 0.f;

#pragma unroll
        for (int k = 0; k < 4; k++) {
            uint32_t aaddr = S0 + OF_AH + (uint32_t)((m0 + lm16) * 144 + k * 32 + lk16);
            uint32_t ah[4];
            LDSM_X4(ah[0], ah[1], ah[2], ah[3], aaddr);
#pragma unroll
            for (int nt = 0; nt < 2; nt++) {
                uint32_t baddr = VB + (uint32_t)((k * 16 + lm16) * 144 + (n0 + nt * 8) * 2);
                uint32_t bf[2];
                LDSM_X2T(bf[0], bf[1], baddr);
                MMAF16(av[nt], ah, bf);
            }
        }
#pragma unroll
        for (int nt = 0; nt < 2; nt++) {
            int b0r = m0 + rq;
            int c = cc * 64 + n0 + nt * 8 + (lane & 3) * 2;
            float v0 = av[nt][0], v1 = av[nt][1], v2 = av[nt][2], v3 = av[nt][3];
            __half2 h01 = __floats2half2_rn(v0, v1);
            __half2 h23 = __floats2half2_rn(v2, v3);
            *(__half2*)(g_vtf + ((size_t)b0r * NL + l) * NC + c)       = h01;
            *(__half2*)(g_vtf + ((size_t)(b0r + 8) * NL + l) * NC + c) = h23;
            gs0  += v0 + v1;
            gss0 += v0 * v0 + v1 * v1;
            gs1  += v2 + v3;
            gss1 += v2 * v2 + v3 * v3;
        }
    }

    gs0  += __shfl_xor_sync(0xffffffffu, gs0, 1);  gs0  += __shfl_xor_sync(0xffffffffu, gs0, 2);
    gss0 += __shfl_xor_sync(0xffffffffu, gss0, 1); gss0 += __shfl_xor_sync(0xffffffffu, gss0, 2);
    gs1  += __shfl_xor_sync(0xffffffffu, gs1, 1);  gs1  += __shfl_xor_sync(0xffffffffu, gs1, 2);
    gss1 += __shfl_xor_sync(0xffffffffu, gss1, 1); gss1 += __shfl_xor_sync(0xffffffffu, gss1, 2);
    if ((lane & 3) == 0) {
        atomicAdd(&smf[(OF_S >> 2) + m0 + rq], gs0);
        atomicAdd(&smf[(OF_S >> 2) + 64 + m0 + rq], gss0);
        atomicAdd(&smf[(OF_S >> 2) + m0 + rq + 8], gs1);
        atomicAdd(&smf[(OF_S >> 2) + 64 + m0 + rq + 8], gss1);
    }
    __syncthreads();
    if (tid < 64) {
        atomicAdd(&g_psum[tid],   smf[(OF_S >> 2) + tid]);
        atomicAdd(&g_psumsq[tid], smf[(OF_S >> 2) + 64 + tid]);
    }
}

// ================= K: stats =================
__global__ void k_stats()
{
    int b = threadIdx.x;
    if (b < NB) {
        const float n = (float)NC * (float)NL;
        float mean = g_psum[b] / n;
        float var  = g_psumsq[b] / n - mean * mean;
        if (var < 0.f) var = 0.f;
        g_mean[b] = mean;
        g_rstd[b] = rsqrtf(var + 1e-5f);
    }
}

// ================= launch =================
extern "C" void kernel_launch(void* const* d_in, const int* in_sizes, int n_in,
                              void* d_out, int out_size)
{
    const float* x     = (const float*)d_in[0];
    const float* Wq    = (const float*)d_in[1];
    const float* Wk    = (const float*)d_in[2];
    const float* Wv    = (const float*)d_in[3];
    const float* Wc    = (const float*)d_in[4];
    const float* Wout  = (const float*)d_in[5];
    const float* gamma = (const float*)d_in[6];
    const float* beta  = (const float*)d_in[7];
    float* out = (float*)d_out;

    cudaFuncSetAttribute(k_attn,    cudaFuncAttributeMaxDynamicSharedMemorySize, SM_ATTN_BYTES);
    cudaFuncSetAttribute(k_gemm<0>, cudaFuncAttributeMaxDynamicSharedMemorySize, SMEM_GEMM0);
    cudaFuncSetAttribute(k_gemm<1>, cudaFuncAttributeMaxDynamicSharedMemorySize, SMEM_GEMM1);

    k_wprep<<<161, 256>>>(Wq, Wk, Wout, Wc, Wv);
    k_prep0<<<dim3(64, 4, 64), 256>>>(x);
    k_gemm<0><<<dim3(2048, 4), 256, SMEM_GEMM0>>>(nullptr, nullptr, nullptr); // z (split), v (single)
    k_attn<<<NL, 512, SM_ATTN_BYTES>>>();
    k_stats<<<1, 64>>>();
    k_gemm<1><<<dim3(2048, 2), 256, SMEM_GEMM1>>>(out, gamma, beta);          // out = Wout x + Wz gn
}